// round 9
// baseline (speedup 1.0000x reference)
#include <cuda_runtime.h>
#include <cstdint>

#define NF    16
#define NP    120
#define EMB   256
#define BATCH 2048

// ---- tcgen05 feature gate: only valid when the compile pass targets sm_103a/f ----
#if defined(__CUDA_ARCH__)
#  if (__CUDA_ARCH__ == 1030) && (defined(__CUDA_ARCH_FEAT_SM103_ALL) || \
       defined(__CUDA_ARCH_SPECIFIC__) || defined(__CUDA_ARCH_FAMILY_SPECIFIC__))
#    define USE_TCGEN 1
#  else
#    define USE_TCGEN 0
#  endif
#else
#  define USE_TCGEN 0
#endif

// ---- shared constants ----
#define BM 128
#define BN 256                    // full EMB per CTA
#define BK 32
#define NSTAGE 2
#define NITER  (EMB / BK)                 // 8 k-slabs
#define A_BYTES (BM * BK * 4)             // 16384
#define B_BYTES (BN * BK * 4)             // 32768
#define STAGE_BYTES (A_BYTES + B_BYTES)   // 49152
#define MBAR_OFF 16   // full0@+0 full1@+8 empty0@+16 empty1@+24 done@+32
#define STAGE0_OFF 1024
#define SMEM_NEEDED (STAGE0_OFF + NSTAGE * STAGE_BYTES)   // 99328
#define SMEM_ALLOC  (SMEM_NEEDED + 1024)                  // 100352 -> 2 CTAs/SM

#define TMEM_COLS 256
// idesc: dtype=F32(1)<<4, atype=TF32(2)<<7, btype=TF32(2)<<10, N/8<<17, M/16<<24
#define IDESC ((1u << 4) | (2u << 7) | (2u << 10) | ((BN / 8) << 17) | ((BM / 16) << 24))

__device__ float g_Wt[(size_t)NP * EMB * EMB];   // W^T scratch, [p][n][k], tf32-rounded

__device__ __forceinline__ float round_tf32(float v) {
    uint32_t u;
    asm("cvt.rna.tf32.f32 %0, %1;" : "=r"(u) : "f"(v));
    return __uint_as_float(u);
}

// ---------------- transpose W[p][k][n] -> g_Wt[p][n][k] ----------------
__global__ void transpose_w(const float* __restrict__ W) {
    __shared__ float t[32][33];
    const int p  = blockIdx.z;
    const int kb = blockIdx.x * 32;
    const int nb = blockIdx.y * 32;
    const float* Wp = W + (size_t)p * EMB * EMB;
    float* Wtp = g_Wt + (size_t)p * EMB * EMB;
    const int tx = threadIdx.x;
#pragma unroll
    for (int i = threadIdx.y; i < 32; i += 8)
        t[i][tx] = round_tf32(Wp[(size_t)(kb + i) * EMB + nb + tx]);
    __syncthreads();
#pragma unroll
    for (int i = threadIdx.y; i < 32; i += 8)
        Wtp[(size_t)(nb + i) * EMB + kb + tx] = t[tx][i];
}

#if USE_TCGEN
// ---------------- tcgen05 helpers ----------------
__device__ __forceinline__ uint32_t smem_u32(const void* p) {
    uint32_t a;
    asm("{ .reg .u64 t; cvta.to.shared.u64 t, %1; cvt.u32.u64 %0, t; }" : "=r"(a) : "l"(p));
    return a;
}
__device__ __forceinline__ uint32_t elect_one() {
    uint32_t pred;
    asm volatile("{ .reg .pred p; elect.sync _|p, 0xFFFFFFFF; selp.b32 %0, 1, 0, p; }" : "=r"(pred));
    return pred;
}
static __device__ __forceinline__ uint64_t make_desc(uint32_t addr) {
    // SW128 K-major: layout=2, version=1, SBO=64 (1024B), LBO=1 (16B)
    return ((uint64_t)2 << 61) | ((uint64_t)1 << 46) | ((uint64_t)64 << 32) |
           ((uint64_t)1 << 16) | (((uint64_t)addr >> 4) & 0x3FFF);
}
#define MBAR_INIT(a, n) asm volatile("mbarrier.init.shared.b64 [%0], %1;" :: "r"(a), "r"(n) : "memory")
__device__ __forceinline__ void mbar_wait(uint32_t mbar, uint32_t parity) {
    uint32_t done;
    asm volatile(
        "{ .reg .pred p; mbarrier.try_wait.parity.acquire.cta.shared::cta.b64 p, [%1], %2; selp.b32 %0, 1, 0, p; }"
        : "=r"(done) : "r"(mbar), "r"(parity) : "memory");
    if (!done) {
        asm volatile(
            "{ .reg .pred P1;\n"
            "W_%=: mbarrier.try_wait.parity.acquire.cta.shared::cta.b64 P1, [%0], %1, 0x989680;\n"
            "@P1 bra.uni D_%=; bra.uni W_%=;\nD_%=: }"
            :: "r"(mbar), "r"(parity) : "memory");
    }
}
__device__ __forceinline__ void cp16(uint32_t dst, const void* src) {
    asm volatile("cp.async.cg.shared.global [%0], [%1], 16;" :: "r"(dst), "l"(src));
}
// .noinc: completion of this thread's prior cp.asyncs performs ONE arrival against
// the barrier's preset count (init count = #producer threads). The default (non-noinc)
// form increments-then-decrements the pending count (net zero) -> deadlock (R8).
__device__ __forceinline__ void cp_async_arrive(uint32_t mbar) {
    asm volatile("cp.async.mbarrier.arrive.noinc.shared::cta.b64 [%0];" :: "r"(mbar) : "memory");
}
__device__ __forceinline__ void mma_tf32_ss(uint32_t d, uint64_t a, uint64_t b,
                                            uint32_t idesc, uint32_t en) {
    asm volatile(
        "{ .reg .pred p; setp.ne.u32 p, %4, 0;\n"
        "tcgen05.mma.cta_group::1.kind::tf32 [%0], %1, %2, %3, {%5,%5,%5,%5}, p; }"
        :: "r"(d), "l"(a), "l"(b), "r"(idesc), "r"(en), "r"(0u) : "memory");
}
#define TC_COMMIT(mbar) \
    asm volatile("tcgen05.commit.cta_group::1.mbarrier::arrive::one.shared::cluster.b64 [%0];" \
                 :: "r"(mbar) : "memory")
#define FENCE_ASYNC()     asm volatile("fence.proxy.async.shared::cta;" ::: "memory")
#define TC_FENCE_AFTER()  asm volatile("tcgen05.fence::after_thread_sync;" ::: "memory")
#define TC_FENCE_BEFORE() asm volatile("tcgen05.fence::before_thread_sync;" ::: "memory")
#define LDTM_X32(r, addr) \
    asm volatile("tcgen05.ld.sync.aligned.32x32b.x32.b32 " \
        "{%0,%1,%2,%3,%4,%5,%6,%7,%8,%9,%10,%11,%12,%13,%14,%15," \
        "%16,%17,%18,%19,%20,%21,%22,%23,%24,%25,%26,%27,%28,%29,%30,%31}, [%32];" \
        : "=r"((r)[0]),"=r"((r)[1]),"=r"((r)[2]),"=r"((r)[3]),"=r"((r)[4]),"=r"((r)[5]),"=r"((r)[6]),"=r"((r)[7]), \
          "=r"((r)[8]),"=r"((r)[9]),"=r"((r)[10]),"=r"((r)[11]),"=r"((r)[12]),"=r"((r)[13]),"=r"((r)[14]),"=r"((r)[15]), \
          "=r"((r)[16]),"=r"((r)[17]),"=r"((r)[18]),"=r"((r)[19]),"=r"((r)[20]),"=r"((r)[21]),"=r"((r)[22]),"=r"((r)[23]), \
          "=r"((r)[24]),"=r"((r)[25]),"=r"((r)[26]),"=r"((r)[27]),"=r"((r)[28]),"=r"((r)[29]),"=r"((r)[30]),"=r"((r)[31]) \
        : "r"(addr))
#define TC_WAIT_LD() asm volatile("tcgen05.wait::ld.sync.aligned;" ::: "memory")

__device__ __forceinline__ uint32_t swz(uint32_t off) { return off ^ ((off >> 3) & 0x70); }
#endif  // USE_TCGEN

#if !USE_TCGEN
// legacy mma.sync helpers (fallback cubin; not selected on GB300)
__device__ __forceinline__ uint32_t f2tf32(float v) {
    uint32_t u;
    asm("cvt.rna.tf32.f32 %0, %1;" : "=r"(u) : "f"(v));
    return u;
}
__device__ __forceinline__ void mma_tf32_16x8x8(float* d, const uint32_t* a, const uint32_t* b) {
    asm volatile(
        "mma.sync.aligned.m16n8k8.row.col.f32.tf32.tf32.f32 "
        "{%0,%1,%2,%3}, {%4,%5,%6,%7}, {%8,%9}, {%0,%1,%2,%3};"
        : "+f"(d[0]), "+f"(d[1]), "+f"(d[2]), "+f"(d[3])
        : "r"(a[0]), "r"(a[1]), "r"(a[2]), "r"(a[3]), "r"(b[0]), "r"(b[1]));
}
#endif

// ================= fused bilinear kernel: one symbol, two arch paths =================
// grid(16, 120), block 256, dynamic smem SMEM_ALLOC
__global__ __launch_bounds__(256, 2)
void bilinear_fused(const float* __restrict__ emb,
                    const float* __restrict__ weight,
                    const float* __restrict__ bias,
                    float* __restrict__ out) {
    const int tid = threadIdx.x;
    const int p   = blockIdx.y;
    // pair p -> (r_idx, c_idx) of triu_indices(16, 1)
    int r_idx = 0, rem = p;
    while (rem >= NF - 1 - r_idx) { rem -= NF - 1 - r_idx; r_idx++; }
    const int c_idx = r_idx + 1 + rem;
    const int m0 = blockIdx.x * BM;

#if USE_TCGEN
    // -------------------------------------------------- tcgen05 tf32 warp-specialized pipeline
    extern __shared__ char smem_raw[];
    const uint32_t base = (smem_u32(smem_raw) + 1023u) & ~1023u;
    const int wid  = tid >> 5;
    const int lane = tid & 31;

    const uint32_t full0  = base + MBAR_OFF;        // full[s]  = full0 + s*8
    const uint32_t empty0 = base + MBAR_OFF + 16;   // empty[s] = empty0 + s*8
    const uint32_t doneb  = base + MBAR_OFF + 32;   // final-MMA barrier (single phase)

    if (wid == 0) {
        asm volatile("tcgen05.alloc.cta_group::1.sync.aligned.shared::cta.b32 [%0], %1;"
                     :: "r"(base), "r"((uint32_t)TMEM_COLS) : "memory");
        // release the per-SM alloc permit immediately (else co-resident CTA serializes)
        asm volatile("tcgen05.relinquish_alloc_permit.cta_group::1.sync.aligned;");
    }
    if (tid == 0) {
#pragma unroll
        for (int s = 0; s < NSTAGE; s++) {
            MBAR_INIT(full0 + s * 8, 128);   // 128 producer-thread completions per stage
            MBAR_INIT(empty0 + s * 8, 1);    // one tcgen05.commit per stage
        }
        MBAR_INIT(doneb, 1);                 // final commit
    }
    __syncthreads();
    uint32_t tmem;
    asm volatile("ld.shared.b32 %0, [%1];" : "=r"(tmem) : "r"(base));

    const float* Wtp = g_Wt + (size_t)p * EMB * EMB;

    if (wid >= 4) {
        // ---------------- producers: warps 4-7 (128 threads), free-running ----------------
        const int ptid = tid - 128;                  // 0..127
        for (int j = 0; j < NITER; j++) {
            const int s = j & (NSTAGE - 1);
            if (j >= NSTAGE)                         // slot reuse: wait MMA of occupant j-NSTAGE
                mbar_wait(empty0 + s * 8, ((j - NSTAGE) >> 1) & 1);
            const uint32_t st = base + STAGE0_OFF + s * STAGE_BYTES;
            const int k0 = j * BK;
#pragma unroll
            for (int i = 0; i < 8; i++) {            // A: 1024 chunks / 128 thr = 8
                int idx = ptid + i * 128;
                int m = idx >> 3, c = idx & 7;
                cp16(st + swz((m << 7) | (c << 4)),
                     emb + ((size_t)(m0 + m) * NF + r_idx) * EMB + k0 + c * 4);
            }
#pragma unroll
            for (int i = 0; i < 16; i++) {           // B: 2048 chunks / 128 thr = 16
                int idx = ptid + i * 128;
                int n = idx >> 3, c = idx & 7;
                cp16(st + A_BYTES + swz((n << 7) | (c << 4)),
                     Wtp + (size_t)n * EMB + k0 + c * 4);
            }
            cp_async_arrive(full0 + s * 8);          // fires when these copies LAND
        }
    } else if (wid == 0) {
        // ---------------- consumer: one elected thread of warp 0 ----------------
        if (elect_one()) {
            for (int it = 0; it < NITER; it++) {
                const int s = it & (NSTAGE - 1);
                mbar_wait(full0 + s * 8, (it >> 1) & 1);
                FENCE_ASYNC();
                const uint32_t st = base + STAGE0_OFF + s * STAGE_BYTES;
                const uint64_t ad = make_desc(st);
                const uint64_t bd = make_desc(st + A_BYTES);
#pragma unroll
                for (int jj = 0; jj < 4; jj++)       // 4 x (K=8) per 32-float slab
                    mma_tf32_ss(tmem, ad + jj * 2, bd + jj * 2, IDESC,
                                (it == 0 && jj == 0) ? 0u : 1u);
                // last iteration signals the dedicated done barrier (single phase,
                // parity 0) -- avoids parity aliasing for threads that skipped the loop.
                // empty[1] is not needed past it=5 (producers stop at j=7).
                TC_COMMIT(it == NITER - 1 ? doneb : empty0 + s * 8);
            }
        }
    }
    // warps 1-3 fall through directly to the final wait.

    // wait for the LAST MMA (single-phase barrier, parity 0)
    mbar_wait(doneb, 0);
    TC_FENCE_AFTER();

    // epilogue: warps 0-3 -> cols [0,128), warps 4-7 -> cols [128,256)
    // row = (wid&3)*32 + lane (warp reads its own TMEM subpartition)
    {
        const int sub  = wid & 3;
        const int half = wid >> 2;
        const int m = m0 + sub * 32 + lane;
        const float* qrow = emb + ((size_t)m * NF + c_idx) * EMB;
        const float* brow = bias + (size_t)p * EMB;
        float* orow = out + ((size_t)m * NP + p) * EMB;
#pragma unroll
        for (int c = 0; c < 4; c++) {
            const int col = half * 128 + c * 32;
            uint32_t r[32];
            LDTM_X32(r, tmem + col);
            TC_WAIT_LD();
#pragma unroll
            for (int jj = 0; jj < 8; jj++) {
                const int gn = col + jj * 4;
                const float4 q  = *(const float4*)(qrow + gn);
                const float4 bb = *(const float4*)(brow + gn);
                float4 o;
                o.x = __uint_as_float(r[jj * 4 + 0]) * q.x + bb.x;
                o.y = __uint_as_float(r[jj * 4 + 1]) * q.y + bb.y;
                o.z = __uint_as_float(r[jj * 4 + 2]) * q.z + bb.z;
                o.w = __uint_as_float(r[jj * 4 + 3]) * q.w + bb.w;
                *(float4*)(orow + gn) = o;
            }
        }
    }
    TC_FENCE_BEFORE();
    __syncthreads();
    if (wid == 0) {
        asm volatile("tcgen05.dealloc.cta_group::1.sync.aligned.b32 %0, %1;"
                     :: "r"(tmem), "r"((uint32_t)TMEM_COLS));
    }

#else
    // -------------------------------------------------- legacy mma.sync tf32 fallback
    // covers the 128x256 CTA tile as two 128x128 passes
    __shared__ uint32_t As[BK * 132];
    __shared__ uint32_t Bs[BK * 132];
    const int lane = tid & 31;
    const int warp = tid >> 5;
    const int warp_m = warp & 3;
    const int warp_n = warp >> 2;
    const float* Wp = weight + (size_t)p * EMB * EMB;
    const int lr = lane >> 2;
    const int lc = lane & 3;

    for (int nb = 0; nb < 2; nb++) {
        const int n0 = nb * 128;
        float acc[2][8][4];
#pragma unroll
        for (int i = 0; i < 2; i++)
#pragma unroll
            for (int j = 0; j < 8; j++)
#pragma unroll
                for (int r = 0; r < 4; r++) acc[i][j][r] = 0.0f;

        for (int k0 = 0; k0 < EMB; k0 += BK) {
            __syncthreads();
#pragma unroll
            for (int it = 0; it < 4; it++) {
                int fid = tid + it * 256;
                int m   = fid >> 3;
                int k4  = fid & 7;
                const float4 v = *(const float4*)(emb + ((size_t)(m0 + m) * NF + r_idx) * EMB + k0 + k4 * 4);
                As[(k4 * 4 + 0) * 132 + m] = f2tf32(v.x);
                As[(k4 * 4 + 1) * 132 + m] = f2tf32(v.y);
                As[(k4 * 4 + 2) * 132 + m] = f2tf32(v.z);
                As[(k4 * 4 + 3) * 132 + m] = f2tf32(v.w);
            }
#pragma unroll
            for (int it = 0; it < 4; it++) {
                int fid = tid + it * 256;
                int k   = fid >> 5;
                int n4  = fid & 31;
                const float4 w = *(const float4*)(Wp + (size_t)(k0 + k) * EMB + n0 + n4 * 4);
                Bs[k * 132 + n4 * 4 + 0] = f2tf32(w.x);
                Bs[k * 132 + n4 * 4 + 1] = f2tf32(w.y);
                Bs[k * 132 + n4 * 4 + 2] = f2tf32(w.z);
                Bs[k * 132 + n4 * 4 + 3] = f2tf32(w.w);
            }
            __syncthreads();

#pragma unroll
            for (int kk = 0; kk < BK; kk += 8) {
                uint32_t a[2][4];
                uint32_t b[8][2];
#pragma unroll
                for (int i = 0; i < 2; i++) {
                    int mbase = warp_m * 32 + i * 16 + lr;
                    a[i][0] = As[(kk + lc) * 132 + mbase];
                    a[i][1] = As[(kk + lc) * 132 + mbase + 8];
                    a[i][2] = As[(kk + lc + 4) * 132 + mbase];
                    a[i][3] = As[(kk + lc + 4) * 132 + mbase + 8];
                }
#pragma unroll
                for (int j = 0; j < 8; j++) {
                    int nbase = warp_n * 64 + j * 8 + lr;
                    b[j][0] = Bs[(kk + lc) * 132 + nbase];
                    b[j][1] = Bs[(kk + lc + 4) * 132 + nbase];
                }
#pragma unroll
                for (int i = 0; i < 2; i++)
#pragma unroll
                    for (int j = 0; j < 8; j++)
                        mma_tf32_16x8x8(acc[i][j], a[i], b[j]);
            }
        }

#pragma unroll
        for (int i = 0; i < 2; i++) {
            const int gm0 = m0 + warp_m * 32 + i * 16 + lr;
#pragma unroll
            for (int j = 0; j < 8; j++) {
                const int gn = n0 + warp_n * 64 + j * 8 + lc * 2;
                const float2 bs = *(const float2*)(bias + (size_t)p * EMB + gn);

                const float2 q0 = *(const float2*)(emb + ((size_t)gm0 * NF + c_idx) * EMB + gn);
                float2 o0;
                o0.x = acc[i][j][0] * q0.x + bs.x;
                o0.y = acc[i][j][1] * q0.y + bs.y;
                *(float2*)(out + ((size_t)gm0 * NP + p) * EMB + gn) = o0;

                const float2 q1 = *(const float2*)(emb + ((size_t)(gm0 + 8) * NF + c_idx) * EMB + gn);
                float2 o1;
                o1.x = acc[i][j][2] * q1.x + bs.x;
                o1.y = acc[i][j][3] * q1.y + bs.y;
                *(float2*)(out + ((size_t)(gm0 + 8) * NP + p) * EMB + gn) = o1;
            }
        }
        __syncthreads();
    }
#endif
}

extern "C" void kernel_launch(void* const* d_in, const int* in_sizes, int n_in,
                              void* d_out, int out_size) {
    const float* emb    = (const float*)d_in[0];
    const float* weight = (const float*)d_in[1];
    const float* bias   = (const float*)d_in[2];
    float* out          = (float*)d_out;

    cudaFuncSetAttribute(bilinear_fused, cudaFuncAttributeMaxDynamicSharedMemorySize, SMEM_ALLOC);

    transpose_w<<<dim3(8, 8, NP), dim3(32, 8)>>>(weight);
    bilinear_fused<<<dim3(BATCH / BM, NP), 256, SMEM_ALLOC>>>(emb, weight, bias, out);
}

// round 12
// speedup vs baseline: 1.1382x; 1.1382x over previous
#include <cuda_runtime.h>
#include <cstdint>

#define NF    16
#define NP    120
#define EMB   256
#define BATCH 2048

// ---- tcgen05 feature gate: only valid when the compile pass targets sm_103a/f ----
#if defined(__CUDA_ARCH__)
#  if (__CUDA_ARCH__ == 1030) && (defined(__CUDA_ARCH_FEAT_SM103_ALL) || \
       defined(__CUDA_ARCH_SPECIFIC__) || defined(__CUDA_ARCH_FAMILY_SPECIFIC__))
#    define USE_TCGEN 1
#  else
#    define USE_TCGEN 0
#  endif
#else
#  define USE_TCGEN 0
#endif

// ---- shared constants ----
#define BM 128
#define BN 256                    // full EMB per CTA
#define BK 32
#define NSTAGE 2
#define NITER  (EMB / BK)                 // 8 k-slabs
#define A_BYTES (BM * BK * 4)             // 16384
#define B_BYTES (BN * BK * 4)             // 32768
#define STAGE_BYTES (A_BYTES + B_BYTES)   // 49152
#define MBAR_OFF 16   // full0@+0 full1@+8 empty0@+16 empty1@+24 done@+32
#define STAGE0_OFF 1024
#define SMEM_NEEDED (STAGE0_OFF + NSTAGE * STAGE_BYTES)   // 99328
#define SMEM_ALLOC  (SMEM_NEEDED + 1024)                  // 100352 -> 2 CTAs/SM

#define TMEM_COLS 256
// idesc: dtype=F32(1)<<4, atype=TF32(2)<<7, btype=TF32(2)<<10, N/8<<17, M/16<<24
#define IDESC ((1u << 4) | (2u << 7) | (2u << 10) | ((BN / 8) << 17) | ((BM / 16) << 24))

// Pre-packed operands: exact SW128-swizzled smem images, slab-major, contiguous.
// g_A[f][slab][m][32 floats]  (raw f32 emb bits)
// g_Wt[p][slab][n][32 floats] (tf32-rounded W^T)
__device__ float g_A [(size_t)NF * NITER * BATCH * BK];   // 33.5 MB
__device__ float g_Wt[(size_t)NP * NITER * EMB * BK];     // 31.5 MB

__device__ __forceinline__ float round_tf32(float v) {
    uint32_t u;
    asm("cvt.rna.tf32.f32 %0, %1;" : "=r"(u) : "f"(v));
    return __uint_as_float(u);
}

// ---------------- pack emb -> g_A (swizzled slab tiles) ----------------
// grid(slab=8, mb=16, f=16), block 256
__global__ void pack_a(const float* __restrict__ emb) {
    const int slab = blockIdx.x, mb = blockIdx.y, f = blockIdx.z;
    const int tid = threadIdx.x;
#pragma unroll
    for (int it = 0; it < 4; it++) {
        int idx = tid + it * 256;            // 0..1023
        int m = idx >> 3, c = idx & 7;
        int gm = mb * 128 + m;
        const float4 v = *(const float4*)(emb + ((size_t)gm * NF + f) * EMB + slab * BK + c * 4);
        *(float4*)(g_A + (((size_t)f * NITER + slab) * BATCH + gm) * BK + ((c ^ (m & 7)) << 2)) = v;
    }
}

// ---------------- pack W[p][k][n] -> g_Wt (transposed, rounded, swizzled) ----------------
// grid(slab=8, nb=8, p=120), block (32,8)
__global__ void pack_w(const float* __restrict__ W) {
    __shared__ float t[32][33];
    const int slab = blockIdx.x;
    const int nb   = blockIdx.y * 32;
    const int p    = blockIdx.z;
    const float* Wp = W + (size_t)p * EMB * EMB;
    const int tx = threadIdx.x;
#pragma unroll
    for (int i = threadIdx.y; i < 32; i += 8)       // t[k_local][n_local]
        t[i][tx] = round_tf32(Wp[(size_t)(slab * BK + i) * EMB + nb + tx]);
    __syncthreads();
    float* dst = g_Wt + ((size_t)p * NITER + slab) * EMB * BK;
#pragma unroll
    for (int i = threadIdx.y; i < 32; i += 8) {     // n = nb+i, k_local = tx
        const int n = nb + i;
        const int c = tx >> 2, sub = tx & 3;
        dst[(size_t)n * BK + ((c ^ (n & 7)) << 2) + sub] = t[tx][i];
    }
}

#if USE_TCGEN
// ---------------- tcgen05 helpers ----------------
__device__ __forceinline__ uint32_t smem_u32(const void* p) {
    uint32_t a;
    asm("{ .reg .u64 t; cvta.to.shared.u64 t, %1; cvt.u32.u64 %0, t; }" : "=r"(a) : "l"(p));
    return a;
}
__device__ __forceinline__ uint32_t elect_one() {
    uint32_t pred;
    asm volatile("{ .reg .pred p; elect.sync _|p, 0xFFFFFFFF; selp.b32 %0, 1, 0, p; }" : "=r"(pred));
    return pred;
}
static __device__ __forceinline__ uint64_t make_desc(uint32_t addr) {
    // SW128 K-major: layout=2, version=1, SBO=64 (1024B), LBO=1 (16B)
    return ((uint64_t)2 << 61) | ((uint64_t)1 << 46) | ((uint64_t)64 << 32) |
           ((uint64_t)1 << 16) | (((uint64_t)addr >> 4) & 0x3FFF);
}
#define MBAR_INIT(a, n) asm volatile("mbarrier.init.shared.b64 [%0], %1;" :: "r"(a), "r"(n) : "memory")
__device__ __forceinline__ void mbar_wait(uint32_t mbar, uint32_t parity) {
    uint32_t done;
    asm volatile(
        "{ .reg .pred p; mbarrier.try_wait.parity.acquire.cta.shared::cta.b64 p, [%1], %2; selp.b32 %0, 1, 0, p; }"
        : "=r"(done) : "r"(mbar), "r"(parity) : "memory");
    if (!done) {
        asm volatile(
            "{ .reg .pred P1;\n"
            "W_%=: mbarrier.try_wait.parity.acquire.cta.shared::cta.b64 P1, [%0], %1, 0x989680;\n"
            "@P1 bra.uni D_%=; bra.uni W_%=;\nD_%=: }"
            :: "r"(mbar), "r"(parity) : "memory");
    }
}
__device__ __forceinline__ void expect_tx(uint32_t mbar, uint32_t bytes) {
    asm volatile("mbarrier.arrive.expect_tx.shared.b64 _, [%0], %1;"
                 :: "r"(mbar), "r"(bytes) : "memory");
}
// bulk copy gmem -> smem, completion feeds tx-count of mbar
__device__ __forceinline__ void bulk_cp(uint32_t dst, const void* src, uint32_t bytes, uint32_t mbar) {
    asm volatile("cp.async.bulk.shared::cta.global.mbarrier::complete_tx::bytes [%0], [%1], %2, [%3];"
                 :: "r"(dst), "l"(src), "r"(bytes), "r"(mbar) : "memory");
}
__device__ __forceinline__ void mma_tf32_ss(uint32_t d, uint64_t a, uint64_t b,
                                            uint32_t idesc, uint32_t en) {
    asm volatile(
        "{ .reg .pred p; setp.ne.u32 p, %4, 0;\n"
        "tcgen05.mma.cta_group::1.kind::tf32 [%0], %1, %2, %3, {%5,%5,%5,%5}, p; }"
        :: "r"(d), "l"(a), "l"(b), "r"(idesc), "r"(en), "r"(0u) : "memory");
}
#define TC_COMMIT(mbar) \
    asm volatile("tcgen05.commit.cta_group::1.mbarrier::arrive::one.shared::cluster.b64 [%0];" \
                 :: "r"(mbar) : "memory")
#define FENCE_ASYNC()     asm volatile("fence.proxy.async.shared::cta;" ::: "memory")
#define TC_FENCE_AFTER()  asm volatile("tcgen05.fence::after_thread_sync;" ::: "memory")
#define TC_FENCE_BEFORE() asm volatile("tcgen05.fence::before_thread_sync;" ::: "memory")
#define LDTM_X32(r, addr) \
    asm volatile("tcgen05.ld.sync.aligned.32x32b.x32.b32 " \
        "{%0,%1,%2,%3,%4,%5,%6,%7,%8,%9,%10,%11,%12,%13,%14,%15," \
        "%16,%17,%18,%19,%20,%21,%22,%23,%24,%25,%26,%27,%28,%29,%30,%31}, [%32];" \
        : "=r"((r)[0]),"=r"((r)[1]),"=r"((r)[2]),"=r"((r)[3]),"=r"((r)[4]),"=r"((r)[5]),"=r"((r)[6]),"=r"((r)[7]), \
          "=r"((r)[8]),"=r"((r)[9]),"=r"((r)[10]),"=r"((r)[11]),"=r"((r)[12]),"=r"((r)[13]),"=r"((r)[14]),"=r"((r)[15]), \
          "=r"((r)[16]),"=r"((r)[17]),"=r"((r)[18]),"=r"((r)[19]),"=r"((r)[20]),"=r"((r)[21]),"=r"((r)[22]),"=r"((r)[23]), \
          "=r"((r)[24]),"=r"((r)[25]),"=r"((r)[26]),"=r"((r)[27]),"=r"((r)[28]),"=r"((r)[29]),"=r"((r)[30]),"=r"((r)[31]) \
        : "r"(addr))
#define TC_WAIT_LD() asm volatile("tcgen05.wait::ld.sync.aligned;" ::: "memory")
#endif  // USE_TCGEN

#if !USE_TCGEN
// legacy mma.sync helpers (fallback cubin; not selected on GB300)
__device__ __forceinline__ uint32_t f2tf32(float v) {
    uint32_t u;
    asm("cvt.rna.tf32.f32 %0, %1;" : "=r"(u) : "f"(v));
    return u;
}
__device__ __forceinline__ void mma_tf32_16x8x8(float* d, const uint32_t* a, const uint32_t* b) {
    asm volatile(
        "mma.sync.aligned.m16n8k8.row.col.f32.tf32.tf32.f32 "
        "{%0,%1,%2,%3}, {%4,%5,%6,%7}, {%8,%9}, {%0,%1,%2,%3};"
        : "+f"(d[0]), "+f"(d[1]), "+f"(d[2]), "+f"(d[3])
        : "r"(a[0]), "r"(a[1]), "r"(a[2]), "r"(a[3]), "r"(b[0]), "r"(b[1]));
}
#endif

// ================= fused bilinear kernel: one symbol, two arch paths =================
// grid(16, 120), block 256, dynamic smem SMEM_ALLOC
__global__ __launch_bounds__(256, 2)
void bilinear_fused(const float* __restrict__ emb,
                    const float* __restrict__ weight,
                    const float* __restrict__ bias,
                    float* __restrict__ out) {
    const int tid = threadIdx.x;
    const int p   = blockIdx.y;
    // pair p -> (r_idx, c_idx) of triu_indices(16, 1)
    int r_idx = 0, rem = p;
    while (rem >= NF - 1 - r_idx) { rem -= NF - 1 - r_idx; r_idx++; }
    const int c_idx = r_idx + 1 + rem;
    const int m0 = blockIdx.x * BM;

#if USE_TCGEN
    // -------------------------------------------------- tcgen05 tf32 bulk-copy pipeline
    extern __shared__ char smem_raw[];
    const uint32_t base = (smem_u32(smem_raw) + 1023u) & ~1023u;
    const int wid  = tid >> 5;
    const int lane = tid & 31;

    const uint32_t full0  = base + MBAR_OFF;        // full[s]  = full0 + s*8
    const uint32_t empty0 = base + MBAR_OFF + 16;   // empty[s] = empty0 + s*8
    const uint32_t doneb  = base + MBAR_OFF + 32;   // final-MMA barrier (single phase)

    if (wid == 0) {
        asm volatile("tcgen05.alloc.cta_group::1.sync.aligned.shared::cta.b32 [%0], %1;"
                     :: "r"(base), "r"((uint32_t)TMEM_COLS) : "memory");
        // release the per-SM alloc permit immediately (else co-resident CTA serializes)
        asm volatile("tcgen05.relinquish_alloc_permit.cta_group::1.sync.aligned;");
    }
    if (tid == 0) {
#pragma unroll
        for (int s = 0; s < NSTAGE; s++) {
            MBAR_INIT(full0 + s * 8, 1);     // 1 arrival (expect_tx) + tx bytes
            MBAR_INIT(empty0 + s * 8, 1);    // one tcgen05.commit per stage
        }
        MBAR_INIT(doneb, 1);                 // final commit
    }
    __syncthreads();
    uint32_t tmem;
    asm volatile("ld.shared.b32 %0, [%1];" : "=r"(tmem) : "r"(base));

    if (wid == 1) {
        // ---------------- producer: one elected thread of warp 1 ----------------
        if (elect_one()) {
            const float* Asrc = g_A + (((size_t)r_idx * NITER) * BATCH + m0) * BK;
            const float* Bsrc = g_Wt + ((size_t)p * NITER) * EMB * BK;
            for (int j = 0; j < NITER; j++) {
                const int s = j & (NSTAGE - 1);
                if (j >= NSTAGE)            // slot reuse: wait MMA of occupant j-NSTAGE
                    mbar_wait(empty0 + s * 8, ((j - NSTAGE) >> 1) & 1);
                const uint32_t st = base + STAGE0_OFF + s * STAGE_BYTES;
                expect_tx(full0 + s * 8, STAGE_BYTES);
                bulk_cp(st,           Asrc + (size_t)j * BATCH * BK, A_BYTES, full0 + s * 8);
                bulk_cp(st + A_BYTES, Bsrc + (size_t)j * EMB * BK,   B_BYTES, full0 + s * 8);
            }
        }
    } else if (wid == 0) {
        // ---------------- consumer: one elected thread of warp 0 ----------------
        if (elect_one()) {
            for (int it = 0; it < NITER; it++) {
                const int s = it & (NSTAGE - 1);
                mbar_wait(full0 + s * 8, (it >> 1) & 1);
                FENCE_ASYNC();
                const uint32_t st = base + STAGE0_OFF + s * STAGE_BYTES;
                const uint64_t ad = make_desc(st);
                const uint64_t bd = make_desc(st + A_BYTES);
#pragma unroll
                for (int jj = 0; jj < 4; jj++)       // 4 x (K=8) per 32-float slab
                    mma_tf32_ss(tmem, ad + jj * 2, bd + jj * 2, IDESC,
                                (it == 0 && jj == 0) ? 0u : 1u);
                // final iteration signals the dedicated done barrier (single phase).
                // empty[1] is not needed past it=5 (producer stops at j=7).
                TC_COMMIT(it == NITER - 1 ? doneb : empty0 + s * 8);
            }
        }
    }
    // warps 2-7 fall through directly to the final wait.

    // wait for the LAST MMA (single-phase barrier, parity 0)
    mbar_wait(doneb, 0);
    TC_FENCE_AFTER();

    // epilogue: warps 0-3 -> cols [0,128), warps 4-7 -> cols [128,256)
    // row = (wid&3)*32 + lane (warp reads its own TMEM subpartition)
    {
        const int sub  = wid & 3;
        const int half = wid >> 2;
        const int m = m0 + sub * 32 + lane;
        const float* qrow = emb + ((size_t)m * NF + c_idx) * EMB;
        const float* brow = bias + (size_t)p * EMB;
        float* orow = out + ((size_t)m * NP + p) * EMB;
#pragma unroll
        for (int c = 0; c < 4; c++) {
            const int col = half * 128 + c * 32;
            uint32_t r[32];
            LDTM_X32(r, tmem + col);
            TC_WAIT_LD();
#pragma unroll
            for (int jj = 0; jj < 8; jj++) {
                const int gn = col + jj * 4;
                const float4 q  = *(const float4*)(qrow + gn);
                const float4 bb = *(const float4*)(brow + gn);
                float4 o;
                o.x = __uint_as_float(r[jj * 4 + 0]) * q.x + bb.x;
                o.y = __uint_as_float(r[jj * 4 + 1]) * q.y + bb.y;
                o.z = __uint_as_float(r[jj * 4 + 2]) * q.z + bb.z;
                o.w = __uint_as_float(r[jj * 4 + 3]) * q.w + bb.w;
                *(float4*)(orow + gn) = o;
            }
        }
    }
    TC_FENCE_BEFORE();
    __syncthreads();
    if (wid == 0) {
        asm volatile("tcgen05.dealloc.cta_group::1.sync.aligned.b32 %0, %1;"
                     :: "r"(tmem), "r"((uint32_t)TMEM_COLS));
    }

#else
    // -------------------------------------------------- legacy mma.sync tf32 fallback
    // covers the 128x256 CTA tile as two 128x128 passes
    __shared__ uint32_t As[BK * 132];
    __shared__ uint32_t Bs[BK * 132];
    const int lane = tid & 31;
    const int warp = tid >> 5;
    const int warp_m = warp & 3;
    const int warp_n = warp >> 2;
    const float* Wp = weight + (size_t)p * EMB * EMB;
    const int lr = lane >> 2;
    const int lc = lane & 3;

    for (int nb = 0; nb < 2; nb++) {
        const int n0 = nb * 128;
        float acc[2][8][4];
#pragma unroll
        for (int i = 0; i < 2; i++)
#pragma unroll
            for (int j = 0; j < 8; j++)
#pragma unroll
                for (int r = 0; r < 4; r++) acc[i][j][r] = 0.0f;

        for (int k0 = 0; k0 < EMB; k0 += BK) {
            __syncthreads();
#pragma unroll
            for (int it = 0; it < 4; it++) {
                int fid = tid + it * 256;
                int m   = fid >> 3;
                int k4  = fid & 7;
                const float4 v = *(const float4*)(emb + ((size_t)(m0 + m) * NF + r_idx) * EMB + k0 + k4 * 4);
                As[(k4 * 4 + 0) * 132 + m] = f2tf32(v.x);
                As[(k4 * 4 + 1) * 132 + m] = f2tf32(v.y);
                As[(k4 * 4 + 2) * 132 + m] = f2tf32(v.z);
                As[(k4 * 4 + 3) * 132 + m] = f2tf32(v.w);
            }
#pragma unroll
            for (int it = 0; it < 4; it++) {
                int fid = tid + it * 256;
                int k   = fid >> 5;
                int n4  = fid & 31;
                const float4 w = *(const float4*)(Wp + (size_t)(k0 + k) * EMB + n0 + n4 * 4);
                Bs[k * 132 + n4 * 4 + 0] = f2tf32(w.x);
                Bs[k * 132 + n4 * 4 + 1] = f2tf32(w.y);
                Bs[k * 132 + n4 * 4 + 2] = f2tf32(w.z);
                Bs[k * 132 + n4 * 4 + 3] = f2tf32(w.w);
            }
            __syncthreads();

#pragma unroll
            for (int kk = 0; kk < BK; kk += 8) {
                uint32_t a[2][4];
                uint32_t b[8][2];
#pragma unroll
                for (int i = 0; i < 2; i++) {
                    int mbase = warp_m * 32 + i * 16 + lr;
                    a[i][0] = As[(kk + lc) * 132 + mbase];
                    a[i][1] = As[(kk + lc) * 132 + mbase + 8];
                    a[i][2] = As[(kk + lc + 4) * 132 + mbase];
                    a[i][3] = As[(kk + lc + 4) * 132 + mbase + 8];
                }
#pragma unroll
                for (int j = 0; j < 8; j++) {
                    int nbase = warp_n * 64 + j * 8 + lr;
                    b[j][0] = Bs[(kk + lc) * 132 + nbase];
                    b[j][1] = Bs[(kk + lc + 4) * 132 + nbase];
                }
#pragma unroll
                for (int i = 0; i < 2; i++)
#pragma unroll
                    for (int j = 0; j < 8; j++)
                        mma_tf32_16x8x8(acc[i][j], a[i], b[j]);
            }
        }

#pragma unroll
        for (int i = 0; i < 2; i++) {
            const int gm0 = m0 + warp_m * 32 + i * 16 + lr;
#pragma unroll
            for (int j = 0; j < 8; j++) {
                const int gn = n0 + warp_n * 64 + j * 8 + lc * 2;
                const float2 bs = *(const float2*)(bias + (size_t)p * EMB + gn);

                const float2 q0 = *(const float2*)(emb + ((size_t)gm0 * NF + c_idx) * EMB + gn);
                float2 o0;
                o0.x = acc[i][j][0] * q0.x + bs.x;
                o0.y = acc[i][j][1] * q0.y + bs.y;
                *(float2*)(out + ((size_t)gm0 * NP + p) * EMB + gn) = o0;

                const float2 q1 = *(const float2*)(emb + ((size_t)(gm0 + 8) * NF + c_idx) * EMB + gn);
                float2 o1;
                o1.x = acc[i][j][2] * q1.x + bs.x;
                o1.y = acc[i][j][3] * q1.y + bs.y;
                *(float2*)(out + ((size_t)(gm0 + 8) * NP + p) * EMB + gn) = o1;
            }
        }
        __syncthreads();
    }
#endif
}

extern "C" void kernel_launch(void* const* d_in, const int* in_sizes, int n_in,
                              void* d_out, int out_size) {
    const float* emb    = (const float*)d_in[0];
    const float* weight = (const float*)d_in[1];
    const float* bias   = (const float*)d_in[2];
    float* out          = (float*)d_out;

    cudaFuncSetAttribute(bilinear_fused, cudaFuncAttributeMaxDynamicSharedMemorySize, SMEM_ALLOC);

    pack_a<<<dim3(NITER, BATCH / BM, NF), 256>>>(emb);
    pack_w<<<dim3(NITER, EMB / 32, NP), dim3(32, 8)>>>(weight);
    bilinear_fused<<<dim3(BATCH / BM, NP), 256, SMEM_ALLOC>>>(emb, weight, bias, out);
}

// round 14
// speedup vs baseline: 1.1410x; 1.0025x over previous
#include <cuda_runtime.h>
#include <cstdint>

#define NF    16
#define NP    120
#define EMB   256
#define BATCH 2048

// ---- tcgen05 feature gate: only valid when the compile pass targets sm_103a/f ----
#if defined(__CUDA_ARCH__)
#  if (__CUDA_ARCH__ == 1030) && (defined(__CUDA_ARCH_FEAT_SM103_ALL) || \
       defined(__CUDA_ARCH_SPECIFIC__) || defined(__CUDA_ARCH_FAMILY_SPECIFIC__))
#    define USE_TCGEN 1
#  else
#    define USE_TCGEN 0
#  endif
#else
#  define USE_TCGEN 0
#endif

// ---- shared constants ----
#define BM 128
#define BN 256                    // full EMB per CTA
#define BK 16                     // 64-byte rows -> SW64 layout
#define NSTAGE 4
#define NITER  (EMB / BK)                 // 16 k-slabs
#define A_BYTES (BM * BK * 4)             // 8192
#define B_BYTES (BN * BK * 4)             // 16384
#define STAGE_BYTES (A_BYTES + B_BYTES)   // 24576
#define MBAR_OFF 16   // full[0..3]@+0..24  empty[0..3]@+32..56  done@+64
#define STAGE0_OFF 1024
#define SMEM_NEEDED (STAGE0_OFF + NSTAGE * STAGE_BYTES)   // 99328
#define SMEM_ALLOC  (SMEM_NEEDED + 1024)                  // 100352 -> 2 CTAs/SM

#define TMEM_COLS 256
// idesc: dtype=F32(1)<<4, atype=TF32(2)<<7, btype=TF32(2)<<10, N/8<<17, M/16<<24
#define IDESC ((1u << 4) | (2u << 7) | (2u << 10) | ((BN / 8) << 17) | ((BM / 16) << 24))

// Pre-packed operands: exact SW64-swizzled smem images, slab-major, contiguous.
// g_A[f][slab16][m][16 floats]  (raw f32 emb bits)
// g_Wt[p][slab16][n][16 floats] (tf32-rounded W^T)
// SW64 swizzle of a 64B row: 16B-chunk c -> c ^ ((row>>1)&3)
__device__ float g_A [(size_t)NF * NITER * BATCH * BK];   // 33.5 MB
__device__ float g_Wt[(size_t)NP * NITER * EMB * BK];     // 31.5 MB

__device__ __forceinline__ float round_tf32(float v) {
    uint32_t u;
    asm("cvt.rna.tf32.f32 %0, %1;" : "=r"(u) : "f"(v));
    return __uint_as_float(u);
}

// ---------------- pack emb -> g_A (SW64 slab tiles) ----------------
// grid(slab=16, mb=16, f=16), block 256
__global__ void pack_a(const float* __restrict__ emb) {
    const int slab = blockIdx.x, mb = blockIdx.y, f = blockIdx.z;
    const int tid = threadIdx.x;
#pragma unroll
    for (int it = 0; it < 2; it++) {
        int idx = tid + it * 256;            // 0..511 (128 rows x 4 chunks)
        int m = idx >> 2, c = idx & 3;
        int gm = mb * 128 + m;
        const float4 v = *(const float4*)(emb + ((size_t)gm * NF + f) * EMB + slab * BK + c * 4);
        *(float4*)(g_A + (((size_t)f * NITER + slab) * BATCH + gm) * BK
                   + ((c ^ ((m >> 1) & 3)) << 2)) = v;
    }
}

// ---------------- pack W[p][k][n] -> g_Wt (transposed, rounded, SW64) ----------------
// grid(kb=8, nb=8, p=120), block (32,8)
__global__ void pack_w(const float* __restrict__ W) {
    __shared__ float t[32][33];
    const int kb = blockIdx.x;              // 32-k block -> two 16-k slabs
    const int nb = blockIdx.y * 32;
    const int p  = blockIdx.z;
    const float* Wp = W + (size_t)p * EMB * EMB;
    const int tx = threadIdx.x;
#pragma unroll
    for (int i = threadIdx.y; i < 32; i += 8)        // t[k_local][n_local]
        t[i][tx] = round_tf32(Wp[(size_t)(kb * 32 + i) * EMB + nb + tx]);
    __syncthreads();
#pragma unroll
    for (int i = threadIdx.y; i < 32; i += 8) {      // n = nb+i, k_local = tx
        const int n    = nb + i;
        const int slab = kb * 2 + (tx >> 4);
        const int kk   = tx & 15;
        const int c = kk >> 2, sub = kk & 3;
        g_Wt[(((size_t)p * NITER + slab) * EMB + n) * BK
             + ((c ^ ((n >> 1) & 3)) << 2) + sub] = t[tx][i];
    }
}

#if USE_TCGEN
// ---------------- tcgen05 helpers ----------------
__device__ __forceinline__ uint32_t smem_u32(const void* p) {
    uint32_t a;
    asm("{ .reg .u64 t; cvta.to.shared.u64 t, %1; cvt.u32.u64 %0, t; }" : "=r"(a) : "l"(p));
    return a;
}
__device__ __forceinline__ uint32_t elect_one() {
    uint32_t pred;
    asm volatile("{ .reg .pred p; elect.sync _|p, 0xFFFFFFFF; selp.b32 %0, 1, 0, p; }" : "=r"(pred));
    return pred;
}
static __device__ __forceinline__ uint64_t make_desc(uint32_t addr) {
    // SW64 K-major: layout=4, version=1, SBO=32 (512B per 8-row block), LBO=1 (16B)
    return ((uint64_t)4 << 61) | ((uint64_t)1 << 46) | ((uint64_t)32 << 32) |
           ((uint64_t)1 << 16) | (((uint64_t)addr >> 4) & 0x3FFF);
}
#define MBAR_INIT(a, n) asm volatile("mbarrier.init.shared.b64 [%0], %1;" :: "r"(a), "r"(n) : "memory")
__device__ __forceinline__ void mbar_wait(uint32_t mbar, uint32_t parity) {
    uint32_t done;
    asm volatile(
        "{ .reg .pred p; mbarrier.try_wait.parity.acquire.cta.shared::cta.b64 p, [%1], %2; selp.b32 %0, 1, 0, p; }"
        : "=r"(done) : "r"(mbar), "r"(parity) : "memory");
    if (!done) {
        asm volatile(
            "{ .reg .pred P1;\n"
            "W_%=: mbarrier.try_wait.parity.acquire.cta.shared::cta.b64 P1, [%0], %1, 0x989680;\n"
            "@P1 bra.uni D_%=; bra.uni W_%=;\nD_%=: }"
            :: "r"(mbar), "r"(parity) : "memory");
    }
}
__device__ __forceinline__ void expect_tx(uint32_t mbar, uint32_t bytes) {
    asm volatile("mbarrier.arrive.expect_tx.shared.b64 _, [%0], %1;"
                 :: "r"(mbar), "r"(bytes) : "memory");
}
// bulk copy gmem -> smem, completion feeds tx-count of mbar
__device__ __forceinline__ void bulk_cp(uint32_t dst, const void* src, uint32_t bytes, uint32_t mbar) {
    asm volatile("cp.async.bulk.shared::cta.global.mbarrier::complete_tx::bytes [%0], [%1], %2, [%3];"
                 :: "r"(dst), "l"(src), "r"(bytes), "r"(mbar) : "memory");
}
__device__ __forceinline__ void mma_tf32_ss(uint32_t d, uint64_t a, uint64_t b,
                                            uint32_t idesc, uint32_t en) {
    asm volatile(
        "{ .reg .pred p; setp.ne.u32 p, %4, 0;\n"
        "tcgen05.mma.cta_group::1.kind::tf32 [%0], %1, %2, %3, {%5,%5,%5,%5}, p; }"
        :: "r"(d), "l"(a), "l"(b), "r"(idesc), "r"(en), "r"(0u) : "memory");
}
#define TC_COMMIT(mbar) \
    asm volatile("tcgen05.commit.cta_group::1.mbarrier::arrive::one.shared::cluster.b64 [%0];" \
                 :: "r"(mbar) : "memory")
#define FENCE_ASYNC()     asm volatile("fence.proxy.async.shared::cta;" ::: "memory")
#define TC_FENCE_AFTER()  asm volatile("tcgen05.fence::after_thread_sync;" ::: "memory")
#define TC_FENCE_BEFORE() asm volatile("tcgen05.fence::before_thread_sync;" ::: "memory")
#define LDTM_X32(r, addr) \
    asm volatile("tcgen05.ld.sync.aligned.32x32b.x32.b32 " \
        "{%0,%1,%2,%3,%4,%5,%6,%7,%8,%9,%10,%11,%12,%13,%14,%15," \
        "%16,%17,%18,%19,%20,%21,%22,%23,%24,%25,%26,%27,%28,%29,%30,%31}, [%32];" \
        : "=r"((r)[0]),"=r"((r)[1]),"=r"((r)[2]),"=r"((r)[3]),"=r"((r)[4]),"=r"((r)[5]),"=r"((r)[6]),"=r"((r)[7]), \
          "=r"((r)[8]),"=r"((r)[9]),"=r"((r)[10]),"=r"((r)[11]),"=r"((r)[12]),"=r"((r)[13]),"=r"((r)[14]),"=r"((r)[15]), \
          "=r"((r)[16]),"=r"((r)[17]),"=r"((r)[18]),"=r"((r)[19]),"=r"((r)[20]),"=r"((r)[21]),"=r"((r)[22]),"=r"((r)[23]), \
          "=r"((r)[24]),"=r"((r)[25]),"=r"((r)[26]),"=r"((r)[27]),"=r"((r)[28]),"=r"((r)[29]),"=r"((r)[30]),"=r"((r)[31]) \
        : "r"(addr))
#define TC_WAIT_LD() asm volatile("tcgen05.wait::ld.sync.aligned;" ::: "memory")
#endif  // USE_TCGEN

#if !USE_TCGEN
// legacy mma.sync helpers (fallback cubin; not selected on GB300)
__device__ __forceinline__ uint32_t f2tf32(float v) {
    uint32_t u;
    asm("cvt.rna.tf32.f32 %0, %1;" : "=r"(u) : "f"(v));
    return u;
}
__device__ __forceinline__ void mma_tf32_16x8x8(float* d, const uint32_t* a, const uint32_t* b) {
    asm volatile(
        "mma.sync.aligned.m16n8k8.row.col.f32.tf32.tf32.f32 "
        "{%0,%1,%2,%3}, {%4,%5,%6,%7}, {%8,%9}, {%0,%1,%2,%3};"
        : "+f"(d[0]), "+f"(d[1]), "+f"(d[2]), "+f"(d[3])
        : "r"(a[0]), "r"(a[1]), "r"(a[2]), "r"(a[3]), "r"(b[0]), "r"(b[1]));
}
#endif

// ================= fused bilinear kernel: one symbol, two arch paths =================
// grid(16, 120), block 256, dynamic smem SMEM_ALLOC
__global__ __launch_bounds__(256, 2)
void bilinear_fused(const float* __restrict__ emb,
                    const float* __restrict__ weight,
                    const float* __restrict__ bias,
                    float* __restrict__ out) {
    const int tid = threadIdx.x;
    const int p   = blockIdx.y;
    // pair p -> (r_idx, c_idx) of triu_indices(16, 1)
    int r_idx = 0, rem = p;
    while (rem >= NF - 1 - r_idx) { rem -= NF - 1 - r_idx; r_idx++; }
    const int c_idx = r_idx + 1 + rem;
    const int m0 = blockIdx.x * BM;

#if USE_TCGEN
    // -------------------------------------------------- tcgen05 tf32 bulk-copy pipeline
    extern __shared__ char smem_raw[];
    const uint32_t base = (smem_u32(smem_raw) + 1023u) & ~1023u;
    const int wid  = tid >> 5;
    const int lane = tid & 31;

    const uint32_t full0  = base + MBAR_OFF;        // full[s]  = full0 + s*8
    const uint32_t empty0 = base + MBAR_OFF + 32;   // empty[s] = empty0 + s*8
    const uint32_t doneb  = base + MBAR_OFF + 64;   // final-MMA barrier (single phase)

    if (wid == 0) {
        asm volatile("tcgen05.alloc.cta_group::1.sync.aligned.shared::cta.b32 [%0], %1;"
                     :: "r"(base), "r"((uint32_t)TMEM_COLS) : "memory");
        // release the per-SM alloc permit immediately (else co-resident CTA serializes)
        asm volatile("tcgen05.relinquish_alloc_permit.cta_group::1.sync.aligned;");
    }
    if (tid == 0) {
#pragma unroll
        for (int s = 0; s < NSTAGE; s++) {
            MBAR_INIT(full0 + s * 8, 1);     // 1 arrival (expect_tx) + tx bytes
            MBAR_INIT(empty0 + s * 8, 1);    // one tcgen05.commit per stage
        }
        MBAR_INIT(doneb, 1);                 // final commit
    }
    __syncthreads();
    uint32_t tmem;
    asm volatile("ld.shared.b32 %0, [%1];" : "=r"(tmem) : "r"(base));

    if (wid == 1) {
        // ---------------- producer: one elected thread of warp 1, runs 3 slabs ahead ----------------
        if (elect_one()) {
            const float* Asrc = g_A + (((size_t)r_idx * NITER) * BATCH + m0) * BK;
            const float* Bsrc = g_Wt + ((size_t)p * NITER) * EMB * BK;
            for (int j = 0; j < NITER; j++) {
                const int s = j & (NSTAGE - 1);
                if (j >= NSTAGE)            // slot reuse: wait MMA of occupant j-NSTAGE
                    mbar_wait(empty0 + s * 8, ((j - NSTAGE) >> 2) & 1);
                const uint32_t st = base + STAGE0_OFF + s * STAGE_BYTES;
                expect_tx(full0 + s * 8, STAGE_BYTES);
                bulk_cp(st,           Asrc + (size_t)j * BATCH * BK, A_BYTES, full0 + s * 8);
                bulk_cp(st + A_BYTES, Bsrc + (size_t)j * EMB * BK,   B_BYTES, full0 + s * 8);
            }
        }
    } else if (wid == 0) {
        // ---------------- consumer: one elected thread of warp 0 ----------------
        if (elect_one()) {
            for (int it = 0; it < NITER; it++) {
                const int s = it & (NSTAGE - 1);
                mbar_wait(full0 + s * 8, (it >> 2) & 1);
                FENCE_ASYNC();
                const uint32_t st = base + STAGE0_OFF + s * STAGE_BYTES;
                const uint64_t ad = make_desc(st);
                const uint64_t bd = make_desc(st + A_BYTES);
#pragma unroll
                for (int jj = 0; jj < 2; jj++)       // 2 x (K=8) per 16-float slab
                    mma_tf32_ss(tmem, ad + jj * 2, bd + jj * 2, IDESC,
                                (it == 0 && jj == 0) ? 0u : 1u);
                // final iteration signals the dedicated done barrier (single phase).
                // empty[3] is not needed past j=11's commit (producer stops at j=15).
                TC_COMMIT(it == NITER - 1 ? doneb : empty0 + s * 8);
            }
        }
    }
    // warps 2-7 fall through directly to the final wait.

    // wait for the LAST MMA (single-phase barrier, parity 0)
    mbar_wait(doneb, 0);
    TC_FENCE_AFTER();

    // epilogue: warps 0-3 -> cols [0,128), warps 4-7 -> cols [128,256)
    // row = (wid&3)*32 + lane (warp reads its own TMEM subpartition)
    {
        const int sub  = wid & 3;
        const int half = wid >> 2;
        const int m = m0 + sub * 32 + lane;
        const float* qrow = emb + ((size_t)m * NF + c_idx) * EMB;
        const float* brow = bias + (size_t)p * EMB;
        float* orow = out + ((size_t)m * NP + p) * EMB;
#pragma unroll
        for (int c = 0; c < 4; c++) {
            const int col = half * 128 + c * 32;
            uint32_t r[32];
            LDTM_X32(r, tmem + col);
            TC_WAIT_LD();
#pragma unroll
            for (int jj = 0; jj < 8; jj++) {
                const int gn = col + jj * 4;
                const float4 q  = *(const float4*)(qrow + gn);
                const float4 bb = *(const float4*)(brow + gn);
                float4 o;
                o.x = __uint_as_float(r[jj * 4 + 0]) * q.x + bb.x;
                o.y = __uint_as_float(r[jj * 4 + 1]) * q.y + bb.y;
                o.z = __uint_as_float(r[jj * 4 + 2]) * q.z + bb.z;
                o.w = __uint_as_float(r[jj * 4 + 3]) * q.w + bb.w;
                *(float4*)(orow + gn) = o;
            }
        }
    }
    TC_FENCE_BEFORE();
    __syncthreads();
    if (wid == 0) {
        asm volatile("tcgen05.dealloc.cta_group::1.sync.aligned.b32 %0, %1;"
                     :: "r"(tmem), "r"((uint32_t)TMEM_COLS));
    }

#else
    // -------------------------------------------------- legacy mma.sync tf32 fallback
    // covers the 128x256 CTA tile as two 128x128 passes (uses raw weight; BK32 tiles)
    __shared__ uint32_t As[32 * 132];
    __shared__ uint32_t Bs[32 * 132];
    const int lane = tid & 31;
    const int warp = tid >> 5;
    const int warp_m = warp & 3;
    const int warp_n = warp >> 2;
    const float* Wp = weight + (size_t)p * EMB * EMB;
    const int lr = lane >> 2;
    const int lc = lane & 3;

    for (int nb = 0; nb < 2; nb++) {
        const int n0 = nb * 128;
        float acc[2][8][4];
#pragma unroll
        for (int i = 0; i < 2; i++)
#pragma unroll
            for (int j = 0; j < 8; j++)
#pragma unroll
                for (int r = 0; r < 4; r++) acc[i][j][r] = 0.0f;

        for (int k0 = 0; k0 < EMB; k0 += 32) {
            __syncthreads();
#pragma unroll
            for (int it = 0; it < 4; it++) {
                int fid = tid + it * 256;
                int m   = fid >> 3;
                int k4  = fid & 7;
                const float4 v = *(const float4*)(emb + ((size_t)(m0 + m) * NF + r_idx) * EMB + k0 + k4 * 4);
                As[(k4 * 4 + 0) * 132 + m] = f2tf32(v.x);
                As[(k4 * 4 + 1) * 132 + m] = f2tf32(v.y);
                As[(k4 * 4 + 2) * 132 + m] = f2tf32(v.z);
                As[(k4 * 4 + 3) * 132 + m] = f2tf32(v.w);
            }
#pragma unroll
            for (int it = 0; it < 4; it++) {
                int fid = tid + it * 256;
                int k   = fid >> 5;
                int n4  = fid & 31;
                const float4 w = *(const float4*)(Wp + (size_t)(k0 + k) * EMB + n0 + n4 * 4);
                Bs[k * 132 + n4 * 4 + 0] = f2tf32(w.x);
                Bs[k * 132 + n4 * 4 + 1] = f2tf32(w.y);
                Bs[k * 132 + n4 * 4 + 2] = f2tf32(w.z);
                Bs[k * 132 + n4 * 4 + 3] = f2tf32(w.w);
            }
            __syncthreads();

#pragma unroll
            for (int kk = 0; kk < 32; kk += 8) {
                uint32_t a[2][4];
                uint32_t b[8][2];
#pragma unroll
                for (int i = 0; i < 2; i++) {
                    int mbase = warp_m * 32 + i * 16 + lr;
                    a[i][0] = As[(kk + lc) * 132 + mbase];
                    a[i][1] = As[(kk + lc) * 132 + mbase + 8];
                    a[i][2] = As[(kk + lc + 4) * 132 + mbase];
                    a[i][3] = As[(kk + lc + 4) * 132 + mbase + 8];
                }
#pragma unroll
                for (int j = 0; j < 8; j++) {
                    int nbase = warp_n * 64 + j * 8 + lr;
                    b[j][0] = Bs[(kk + lc) * 132 + nbase];
                    b[j][1] = Bs[(kk + lc + 4) * 132 + nbase];
                }
#pragma unroll
                for (int i = 0; i < 2; i++)
#pragma unroll
                    for (int j = 0; j < 8; j++)
                        mma_tf32_16x8x8(acc[i][j], a[i], b[j]);
            }
        }

#pragma unroll
        for (int i = 0; i < 2; i++) {
            const int gm0 = m0 + warp_m * 32 + i * 16 + lr;
#pragma unroll
            for (int j = 0; j < 8; j++) {
                const int gn = n0 + warp_n * 64 + j * 8 + lc * 2;
                const float2 bs = *(const float2*)(bias + (size_t)p * EMB + gn);

                const float2 q0 = *(const float2*)(emb + ((size_t)gm0 * NF + c_idx) * EMB + gn);
                float2 o0;
                o0.x = acc[i][j][0] * q0.x + bs.x;
                o0.y = acc[i][j][1] * q0.y + bs.y;
                *(float2*)(out + ((size_t)gm0 * NP + p) * EMB + gn) = o0;

                const float2 q1 = *(const float2*)(emb + ((size_t)(gm0 + 8) * NF + c_idx) * EMB + gn);
                float2 o1;
                o1.x = acc[i][j][2] * q1.x + bs.x;
                o1.y = acc[i][j][3] * q1.y + bs.y;
                *(float2*)(out + ((size_t)(gm0 + 8) * NP + p) * EMB + gn) = o1;
            }
        }
        __syncthreads();
    }
#endif
}

extern "C" void kernel_launch(void* const* d_in, const int* in_sizes, int n_in,
                              void* d_out, int out_size) {
    const float* emb    = (const float*)d_in[0];
    const float* weight = (const float*)d_in[1];
    const float* bias   = (const float*)d_in[2];
    float* out          = (float*)d_out;

    cudaFuncSetAttribute(bilinear_fused, cudaFuncAttributeMaxDynamicSharedMemorySize, SMEM_ALLOC);

    pack_a<<<dim3(NITER, BATCH / BM, NF), 256>>>(emb);
    pack_w<<<dim3(8, EMB / 32, NP), dim3(32, 8)>>>(weight);
    bilinear_fused<<<dim3(BATCH / BM, NP), 256, SMEM_ALLOC>>>(emb, weight, bias, out);
}

// round 15
// speedup vs baseline: 1.3545x; 1.1871x over previous
#include <cuda_runtime.h>
#include <cstdint>

#define NF    16
#define NP    120
#define EMB   256
#define BATCH 2048

// ---- tcgen05 feature gate: only valid when the compile pass targets sm_103a/f ----
#if defined(__CUDA_ARCH__)
#  if (__CUDA_ARCH__ == 1030) && (defined(__CUDA_ARCH_FEAT_SM103_ALL) || \
       defined(__CUDA_ARCH_SPECIFIC__) || defined(__CUDA_ARCH_FAMILY_SPECIFIC__))
#    define USE_TCGEN 1
#  else
#    define USE_TCGEN 0
#  endif
#else
#  define USE_TCGEN 0
#endif

// ---- shared constants ----
#define BM 128
#define BN 256                    // full EMB per CTA
#define BK 16                     // 64-byte rows -> SW64 layout
#define NSTAGE 4
#define NITER  (EMB / BK)                 // 16 k-slabs
#define A_BYTES (BM * BK * 4)             // 8192
#define B_BYTES (BN * BK * 4)             // 16384
#define STAGE_BYTES (A_BYTES + B_BYTES)   // 24576
#define MBAR_OFF 16   // full[0..3]@+0..24  empty[0..3]@+32..56  done@+64
#define STAGE0_OFF 1024
#define SMEM_NEEDED (STAGE0_OFF + NSTAGE * STAGE_BYTES)   // 99328
#define SMEM_ALLOC  (SMEM_NEEDED + 1024)                  // 100352 -> 2 CTAs/SM

// epilogue staging buffers (reuse stage smem after mainloop)
#define EPI_STRIDE 65                      // floats per row (64 + 1 pad -> conflict-free lane reads)
#define Q_S_OFF   1024
#define OUT_S_OFF (Q_S_OFF + 128 * EPI_STRIDE * 4)     // 1024 + 33280 = 34304; end 67584 < 99328

#define TMEM_COLS 256
// idesc: dtype=F32(1)<<4, atype=TF32(2)<<7, btype=TF32(2)<<10, N/8<<17, M/16<<24
#define IDESC ((1u << 4) | (2u << 7) | (2u << 10) | ((BN / 8) << 17) | ((BM / 16) << 24))

// Pre-packed operands: exact SW64-swizzled smem images, slab-major, contiguous.
// g_A[f][slab16][m][16 floats]  (raw f32 emb bits)
// g_Wt[p][slab16][n][16 floats] (tf32-rounded W^T)
// SW64 swizzle of a 64B row: 16B-chunk c -> c ^ ((row>>1)&3)
__device__ float g_A [(size_t)NF * NITER * BATCH * BK];   // 33.5 MB
__device__ float g_Wt[(size_t)NP * NITER * EMB * BK];     // 31.5 MB

__device__ __forceinline__ float round_tf32(float v) {
    uint32_t u;
    asm("cvt.rna.tf32.f32 %0, %1;" : "=r"(u) : "f"(v));
    return __uint_as_float(u);
}

// ---------------- pack emb -> g_A (SW64 slab tiles) ----------------
// grid(slab=16, mb=16, f=16), block 256
__global__ void pack_a(const float* __restrict__ emb) {
    const int slab = blockIdx.x, mb = blockIdx.y, f = blockIdx.z;
    const int tid = threadIdx.x;
#pragma unroll
    for (int it = 0; it < 2; it++) {
        int idx = tid + it * 256;            // 0..511 (128 rows x 4 chunks)
        int m = idx >> 2, c = idx & 3;
        int gm = mb * 128 + m;
        const float4 v = *(const float4*)(emb + ((size_t)gm * NF + f) * EMB + slab * BK + c * 4);
        *(float4*)(g_A + (((size_t)f * NITER + slab) * BATCH + gm) * BK
                   + ((c ^ ((m >> 1) & 3)) << 2)) = v;
    }
}

// ---------------- pack W[p][k][n] -> g_Wt (transposed, rounded, SW64) ----------------
// grid(kb=8, nb=8, p=120), block (32,8)
__global__ void pack_w(const float* __restrict__ W) {
    __shared__ float t[32][33];
    const int kb = blockIdx.x;              // 32-k block -> two 16-k slabs
    const int nb = blockIdx.y * 32;
    const int p  = blockIdx.z;
    const float* Wp = W + (size_t)p * EMB * EMB;
    const int tx = threadIdx.x;
#pragma unroll
    for (int i = threadIdx.y; i < 32; i += 8)        // t[k_local][n_local]
        t[i][tx] = round_tf32(Wp[(size_t)(kb * 32 + i) * EMB + nb + tx]);
    __syncthreads();
#pragma unroll
    for (int i = threadIdx.y; i < 32; i += 8) {      // n = nb+i, k_local = tx
        const int n    = nb + i;
        const int slab = kb * 2 + (tx >> 4);
        const int kk   = tx & 15;
        const int c = kk >> 2, sub = kk & 3;
        g_Wt[(((size_t)p * NITER + slab) * EMB + n) * BK
             + ((c ^ ((n >> 1) & 3)) << 2) + sub] = t[tx][i];
    }
}

#if USE_TCGEN
// ---------------- tcgen05 helpers ----------------
__device__ __forceinline__ uint32_t smem_u32(const void* p) {
    uint32_t a;
    asm("{ .reg .u64 t; cvta.to.shared.u64 t, %1; cvt.u32.u64 %0, t; }" : "=r"(a) : "l"(p));
    return a;
}
__device__ __forceinline__ uint32_t elect_one() {
    uint32_t pred;
    asm volatile("{ .reg .pred p; elect.sync _|p, 0xFFFFFFFF; selp.b32 %0, 1, 0, p; }" : "=r"(pred));
    return pred;
}
static __device__ __forceinline__ uint64_t make_desc(uint32_t addr) {
    // SW64 K-major: layout=4, version=1, SBO=32 (512B per 8-row block), LBO=1 (16B)
    return ((uint64_t)4 << 61) | ((uint64_t)1 << 46) | ((uint64_t)32 << 32) |
           ((uint64_t)1 << 16) | (((uint64_t)addr >> 4) & 0x3FFF);
}
#define MBAR_INIT(a, n) asm volatile("mbarrier.init.shared.b64 [%0], %1;" :: "r"(a), "r"(n) : "memory")
__device__ __forceinline__ void mbar_wait(uint32_t mbar, uint32_t parity) {
    uint32_t done;
    asm volatile(
        "{ .reg .pred p; mbarrier.try_wait.parity.acquire.cta.shared::cta.b64 p, [%1], %2; selp.b32 %0, 1, 0, p; }"
        : "=r"(done) : "r"(mbar), "r"(parity) : "memory");
    if (!done) {
        asm volatile(
            "{ .reg .pred P1;\n"
            "W_%=: mbarrier.try_wait.parity.acquire.cta.shared::cta.b64 P1, [%0], %1, 0x989680;\n"
            "@P1 bra.uni D_%=; bra.uni W_%=;\nD_%=: }"
            :: "r"(mbar), "r"(parity) : "memory");
    }
}
__device__ __forceinline__ void expect_tx(uint32_t mbar, uint32_t bytes) {
    asm volatile("mbarrier.arrive.expect_tx.shared.b64 _, [%0], %1;"
                 :: "r"(mbar), "r"(bytes) : "memory");
}
// bulk copy gmem -> smem, completion feeds tx-count of mbar
__device__ __forceinline__ void bulk_cp(uint32_t dst, const void* src, uint32_t bytes, uint32_t mbar) {
    asm volatile("cp.async.bulk.shared::cta.global.mbarrier::complete_tx::bytes [%0], [%1], %2, [%3];"
                 :: "r"(dst), "l"(src), "r"(bytes), "r"(mbar) : "memory");
}
__device__ __forceinline__ void mma_tf32_ss(uint32_t d, uint64_t a, uint64_t b,
                                            uint32_t idesc, uint32_t en) {
    asm volatile(
        "{ .reg .pred p; setp.ne.u32 p, %4, 0;\n"
        "tcgen05.mma.cta_group::1.kind::tf32 [%0], %1, %2, %3, {%5,%5,%5,%5}, p; }"
        :: "r"(d), "l"(a), "l"(b), "r"(idesc), "r"(en), "r"(0u) : "memory");
}
#define TC_COMMIT(mbar) \
    asm volatile("tcgen05.commit.cta_group::1.mbarrier::arrive::one.shared::cluster.b64 [%0];" \
                 :: "r"(mbar) : "memory")
#define FENCE_ASYNC()     asm volatile("fence.proxy.async.shared::cta;" ::: "memory")
#define TC_FENCE_AFTER()  asm volatile("tcgen05.fence::after_thread_sync;" ::: "memory")
#define TC_FENCE_BEFORE() asm volatile("tcgen05.fence::before_thread_sync;" ::: "memory")
#define LDTM_X32(r, addr) \
    asm volatile("tcgen05.ld.sync.aligned.32x32b.x32.b32 " \
        "{%0,%1,%2,%3,%4,%5,%6,%7,%8,%9,%10,%11,%12,%13,%14,%15," \
        "%16,%17,%18,%19,%20,%21,%22,%23,%24,%25,%26,%27,%28,%29,%30,%31}, [%32];" \
        : "=r"((r)[0]),"=r"((r)[1]),"=r"((r)[2]),"=r"((r)[3]),"=r"((r)[4]),"=r"((r)[5]),"=r"((r)[6]),"=r"((r)[7]), \
          "=r"((r)[8]),"=r"((r)[9]),"=r"((r)[10]),"=r"((r)[11]),"=r"((r)[12]),"=r"((r)[13]),"=r"((r)[14]),"=r"((r)[15]), \
          "=r"((r)[16]),"=r"((r)[17]),"=r"((r)[18]),"=r"((r)[19]),"=r"((r)[20]),"=r"((r)[21]),"=r"((r)[22]),"=r"((r)[23]), \
          "=r"((r)[24]),"=r"((r)[25]),"=r"((r)[26]),"=r"((r)[27]),"=r"((r)[28]),"=r"((r)[29]),"=r"((r)[30]),"=r"((r)[31]) \
        : "r"(addr))
#define TC_WAIT_LD() asm volatile("tcgen05.wait::ld.sync.aligned;" ::: "memory")
#endif  // USE_TCGEN

#if !USE_TCGEN
// legacy mma.sync helpers (fallback cubin; not selected on GB300)
__device__ __forceinline__ uint32_t f2tf32(float v) {
    uint32_t u;
    asm("cvt.rna.tf32.f32 %0, %1;" : "=r"(u) : "f"(v));
    return u;
}
__device__ __forceinline__ void mma_tf32_16x8x8(float* d, const uint32_t* a, const uint32_t* b) {
    asm volatile(
        "mma.sync.aligned.m16n8k8.row.col.f32.tf32.tf32.f32 "
        "{%0,%1,%2,%3}, {%4,%5,%6,%7}, {%8,%9}, {%0,%1,%2,%3};"
        : "+f"(d[0]), "+f"(d[1]), "+f"(d[2]), "+f"(d[3])
        : "r"(a[0]), "r"(a[1]), "r"(a[2]), "r"(a[3]), "r"(b[0]), "r"(b[1]));
}
#endif

// ================= fused bilinear kernel: one symbol, two arch paths =================
// grid(16, 120), block 256, dynamic smem SMEM_ALLOC
__global__ __launch_bounds__(256, 2)
void bilinear_fused(const float* __restrict__ emb,
                    const float* __restrict__ weight,
                    const float* __restrict__ bias,
                    float* __restrict__ out) {
    const int tid = threadIdx.x;
    const int p   = blockIdx.y;
    // pair p -> (r_idx, c_idx) of triu_indices(16, 1)
    int r_idx = 0, rem = p;
    while (rem >= NF - 1 - r_idx) { rem -= NF - 1 - r_idx; r_idx++; }
    const int c_idx = r_idx + 1 + rem;
    const int m0 = blockIdx.x * BM;

#if USE_TCGEN
    // -------------------------------------------------- tcgen05 tf32 bulk-copy pipeline
    extern __shared__ char smem_raw[];
    const uint32_t raw_u32 = smem_u32(smem_raw);
    const uint32_t base = (raw_u32 + 1023u) & ~1023u;
    const uint32_t pad  = base - raw_u32;
    const int wid  = tid >> 5;
    const int lane = tid & 31;

    const uint32_t full0  = base + MBAR_OFF;        // full[s]  = full0 + s*8
    const uint32_t empty0 = base + MBAR_OFF + 32;   // empty[s] = empty0 + s*8
    const uint32_t doneb  = base + MBAR_OFF + 64;   // final-MMA barrier (single phase)

    if (wid == 0) {
        asm volatile("tcgen05.alloc.cta_group::1.sync.aligned.shared::cta.b32 [%0], %1;"
                     :: "r"(base), "r"((uint32_t)TMEM_COLS) : "memory");
        // release the per-SM alloc permit immediately (else co-resident CTA serializes)
        asm volatile("tcgen05.relinquish_alloc_permit.cta_group::1.sync.aligned;");
    }
    if (tid == 0) {
#pragma unroll
        for (int s = 0; s < NSTAGE; s++) {
            MBAR_INIT(full0 + s * 8, 1);     // 1 arrival (expect_tx) + tx bytes
            MBAR_INIT(empty0 + s * 8, 1);    // one tcgen05.commit per stage
        }
        MBAR_INIT(doneb, 1);                 // final commit
    }
    __syncthreads();
    uint32_t tmem;
    asm volatile("ld.shared.b32 %0, [%1];" : "=r"(tmem) : "r"(base));

    if (wid == 1) {
        // ---------------- producer: one elected thread of warp 1, runs 3 slabs ahead ----------------
        if (elect_one()) {
            const float* Asrc = g_A + (((size_t)r_idx * NITER) * BATCH + m0) * BK;
            const float* Bsrc = g_Wt + ((size_t)p * NITER) * EMB * BK;
            for (int j = 0; j < NITER; j++) {
                const int s = j & (NSTAGE - 1);
                if (j >= NSTAGE)            // slot reuse: wait MMA of occupant j-NSTAGE
                    mbar_wait(empty0 + s * 8, ((j - NSTAGE) >> 2) & 1);
                const uint32_t st = base + STAGE0_OFF + s * STAGE_BYTES;
                expect_tx(full0 + s * 8, STAGE_BYTES);
                bulk_cp(st,           Asrc + (size_t)j * BATCH * BK, A_BYTES, full0 + s * 8);
                bulk_cp(st + A_BYTES, Bsrc + (size_t)j * EMB * BK,   B_BYTES, full0 + s * 8);
            }
        }
    } else if (wid == 0) {
        // ---------------- consumer: one elected thread of warp 0 ----------------
        if (elect_one()) {
            for (int it = 0; it < NITER; it++) {
                const int s = it & (NSTAGE - 1);
                mbar_wait(full0 + s * 8, (it >> 2) & 1);
                FENCE_ASYNC();
                const uint32_t st = base + STAGE0_OFF + s * STAGE_BYTES;
                const uint64_t ad = make_desc(st);
                const uint64_t bd = make_desc(st + A_BYTES);
#pragma unroll
                for (int jj = 0; jj < 2; jj++)       // 2 x (K=8) per 16-float slab
                    mma_tf32_ss(tmem, ad + jj * 2, bd + jj * 2, IDESC,
                                (it == 0 && jj == 0) ? 0u : 1u);
                // final iteration signals the dedicated done barrier (single phase).
                TC_COMMIT(it == NITER - 1 ? doneb : empty0 + s * 8);
            }
        }
    }
    // warps 2-7 fall through directly to the final wait.

    // wait for the LAST MMA (single-phase barrier, parity 0)
    mbar_wait(doneb, 0);
    TC_FENCE_AFTER();

    // ---------------- epilogue: smem-staged, fully coalesced q loads / out stores ----------------
    // All MMAs complete and all bulk copies consumed -> stage smem is reusable.
    {
        float* q_s   = (float*)(smem_raw + pad + Q_S_OFF);     // [128][EPI_STRIDE]
        float* out_s = (float*)(smem_raw + pad + OUT_S_OFF);   // [128][EPI_STRIDE]
        const float* brow = bias + (size_t)p * EMB;
        const int sub  = wid & 3;                 // TMEM row subpartition (rows sub*32+lane)
        const int colw = (wid >> 2) * 32;         // col offset within the 64-col chunk
        const int mrow = sub * 32 + lane;

#pragma unroll
        for (int ch = 0; ch < 4; ch++) {
            const int c0 = ch * 64;               // global col base of this chunk
            __syncthreads();                       // protect buffer reuse across chunks
            // stage q tile [128 x 64], coalesced: 16 lanes per row, 256B runs
#pragma unroll
            for (int i = 0; i < 8; i++) {
                int idx = tid + i * 256;           // 0..2047
                int row = idx >> 4, c4 = idx & 15;
                const float4 v = *(const float4*)(emb + ((size_t)(m0 + row) * NF + c_idx) * EMB + c0 + c4 * 4);
                float* d = q_s + row * EPI_STRIDE + c4 * 4;
                d[0] = v.x; d[1] = v.y; d[2] = v.z; d[3] = v.w;
            }
            __syncthreads();
            // LDTM 32 cols per warp + multiply + stage out
            {
                uint32_t r[32];
                LDTM_X32(r, tmem + c0 + colw);
                TC_WAIT_LD();
                const float* qs = q_s   + mrow * EPI_STRIDE + colw;
                float*       os = out_s + mrow * EPI_STRIDE + colw;
#pragma unroll
                for (int jj = 0; jj < 8; jj++) {
                    const float4 bb = *(const float4*)(brow + c0 + colw + jj * 4);
                    os[jj * 4 + 0] = __uint_as_float(r[jj * 4 + 0]) * qs[jj * 4 + 0] + bb.x;
                    os[jj * 4 + 1] = __uint_as_float(r[jj * 4 + 1]) * qs[jj * 4 + 1] + bb.y;
                    os[jj * 4 + 2] = __uint_as_float(r[jj * 4 + 2]) * qs[jj * 4 + 2] + bb.z;
                    os[jj * 4 + 3] = __uint_as_float(r[jj * 4 + 3]) * qs[jj * 4 + 3] + bb.w;
                }
            }
            __syncthreads();
            // store out tile [128 x 64], coalesced float4 stores
#pragma unroll
            for (int i = 0; i < 8; i++) {
                int idx = tid + i * 256;
                int row = idx >> 4, c4 = idx & 15;
                const float* s = out_s + row * EPI_STRIDE + c4 * 4;
                float4 v; v.x = s[0]; v.y = s[1]; v.z = s[2]; v.w = s[3];
                *(float4*)(out + ((size_t)(m0 + row) * NP + p) * EMB + c0 + c4 * 4) = v;
            }
        }
    }
    TC_FENCE_BEFORE();
    __syncthreads();
    if (wid == 0) {
        asm volatile("tcgen05.dealloc.cta_group::1.sync.aligned.b32 %0, %1;"
                     :: "r"(tmem), "r"((uint32_t)TMEM_COLS));
    }

#else
    // -------------------------------------------------- legacy mma.sync tf32 fallback
    // covers the 128x256 CTA tile as two 128x128 passes (uses raw weight; BK32 tiles)
    __shared__ uint32_t As[32 * 132];
    __shared__ uint32_t Bs[32 * 132];
    const int lane = tid & 31;
    const int warp = tid >> 5;
    const int warp_m = warp & 3;
    const int warp_n = warp >> 2;
    const float* Wp = weight + (size_t)p * EMB * EMB;
    const int lr = lane >> 2;
    const int lc = lane & 3;

    for (int nb = 0; nb < 2; nb++) {
        const int n0 = nb * 128;
        float acc[2][8][4];
#pragma unroll
        for (int i = 0; i < 2; i++)
#pragma unroll
            for (int j = 0; j < 8; j++)
#pragma unroll
                for (int r = 0; r < 4; r++) acc[i][j][r] = 0.0f;

        for (int k0 = 0; k0 < EMB; k0 += 32) {
            __syncthreads();
#pragma unroll
            for (int it = 0; it < 4; it++) {
                int fid = tid + it * 256;
                int m   = fid >> 3;
                int k4  = fid & 7;
                const float4 v = *(const float4*)(emb + ((size_t)(m0 + m) * NF + r_idx) * EMB + k0 + k4 * 4);
                As[(k4 * 4 + 0) * 132 + m] = f2tf32(v.x);
                As[(k4 * 4 + 1) * 132 + m] = f2tf32(v.y);
                As[(k4 * 4 + 2) * 132 + m] = f2tf32(v.z);
                As[(k4 * 4 + 3) * 132 + m] = f2tf32(v.w);
            }
#pragma unroll
            for (int it = 0; it < 4; it++) {
                int fid = tid + it * 256;
                int k   = fid >> 5;
                int n4  = fid & 31;
                const float4 w = *(const float4*)(Wp + (size_t)(k0 + k) * EMB + n0 + n4 * 4);
                Bs[k * 132 + n4 * 4 + 0] = f2tf32(w.x);
                Bs[k * 132 + n4 * 4 + 1] = f2tf32(w.y);
                Bs[k * 132 + n4 * 4 + 2] = f2tf32(w.z);
                Bs[k * 132 + n4 * 4 + 3] = f2tf32(w.w);
            }
            __syncthreads();

#pragma unroll
            for (int kk = 0; kk < 32; kk += 8) {
                uint32_t a[2][4];
                uint32_t b[8][2];
#pragma unroll
                for (int i = 0; i < 2; i++) {
                    int mbase = warp_m * 32 + i * 16 + lr;
                    a[i][0] = As[(kk + lc) * 132 + mbase];
                    a[i][1] = As[(kk + lc) * 132 + mbase + 8];
                    a[i][2] = As[(kk + lc + 4) * 132 + mbase];
                    a[i][3] = As[(kk + lc + 4) * 132 + mbase + 8];
                }
#pragma unroll
                for (int j = 0; j < 8; j++) {
                    int nbase = warp_n * 64 + j * 8 + lr;
                    b[j][0] = Bs[(kk + lc) * 132 + nbase];
                    b[j][1] = Bs[(kk + lc + 4) * 132 + nbase];
                }
#pragma unroll
                for (int i = 0; i < 2; i++)
#pragma unroll
                    for (int j = 0; j < 8; j++)
                        mma_tf32_16x8x8(acc[i][j], a[i], b[j]);
            }
        }

#pragma unroll
        for (int i = 0; i < 2; i++) {
            const int gm0 = m0 + warp_m * 32 + i * 16 + lr;
#pragma unroll
            for (int j = 0; j < 8; j++) {
                const int gn = n0 + warp_n * 64 + j * 8 + lc * 2;
                const float2 bs = *(const float2*)(bias + (size_t)p * EMB + gn);

                const float2 q0 = *(const float2*)(emb + ((size_t)gm0 * NF + c_idx) * EMB + gn);
                float2 o0;
                o0.x = acc[i][j][0] * q0.x + bs.x;
                o0.y = acc[i][j][1] * q0.y + bs.y;
                *(float2*)(out + ((size_t)gm0 * NP + p) * EMB + gn) = o0;

                const float2 q1 = *(const float2*)(emb + ((size_t)(gm0 + 8) * NF + c_idx) * EMB + gn);
                float2 o1;
                o1.x = acc[i][j][2] * q1.x + bs.x;
                o1.y = acc[i][j][3] * q1.y + bs.y;
                *(float2*)(out + ((size_t)(gm0 + 8) * NP + p) * EMB + gn) = o1;
            }
        }
        __syncthreads();
    }
#endif
}

extern "C" void kernel_launch(void* const* d_in, const int* in_sizes, int n_in,
                              void* d_out, int out_size) {
    const float* emb    = (const float*)d_in[0];
    const float* weight = (const float*)d_in[1];
    const float* bias   = (const float*)d_in[2];
    float* out          = (float*)d_out;

    cudaFuncSetAttribute(bilinear_fused, cudaFuncAttributeMaxDynamicSharedMemorySize, SMEM_ALLOC);

    pack_a<<<dim3(NITER, BATCH / BM, NF), 256>>>(emb);
    pack_w<<<dim3(8, EMB / 32, NP), dim3(32, 8)>>>(weight);
    bilinear_fused<<<dim3(BATCH / BM, NP), 256, SMEM_ALLOC>>>(emb, weight, bias, out);
}

// round 16
// speedup vs baseline: 1.8230x; 1.3459x over previous
#include <cuda_runtime.h>
#include <cstdint>

#define NF    16
#define NP    120
#define EMB   256
#define BATCH 2048

// ---- tcgen05 feature gate: only valid when the compile pass targets sm_103a/f ----
#if defined(__CUDA_ARCH__)
#  if (__CUDA_ARCH__ == 1030) && (defined(__CUDA_ARCH_FEAT_SM103_ALL) || \
       defined(__CUDA_ARCH_SPECIFIC__) || defined(__CUDA_ARCH_FAMILY_SPECIFIC__))
#    define USE_TCGEN 1
#  else
#    define USE_TCGEN 0
#  endif
#else
#  define USE_TCGEN 0
#endif

// ---- shared constants ----
#define BM 128
#define BN 256                    // full EMB per CTA
#define BK 16                     // 64-byte rows -> SW64 layout
#define NSTAGE 4
#define NITER  (EMB / BK)                 // 16 k-slabs
#define A_BYTES (BM * BK * 4)             // 8192
#define B_BYTES (BN * BK * 4)             // 16384
#define BHALF   (B_BYTES / 2)             // 8192 (per-rank multicast slice)
#define STAGE_BYTES (A_BYTES + B_BYTES)   // 24576
#define MBAR_OFF 16   // full[0..3]@+0..24  empty[0..3]@+32..56  done@+64
#define STAGE0_OFF 1024
#define SMEM_NEEDED (STAGE0_OFF + NSTAGE * STAGE_BYTES)   // 99328
#define SMEM_ALLOC  (SMEM_NEEDED + 1024)                  // 100352 -> 2 CTAs/SM

// epilogue staging buffers (reuse stage smem after mainloop)
#define EPI_STRIDE 65                      // floats per row (64 + 1 pad -> conflict-free lane reads)
#define Q_S_OFF   1024
#define OUT_S_OFF (Q_S_OFF + 128 * EPI_STRIDE * 4)     // end 67584 < 99328

#define TMEM_COLS 256
// idesc: dtype=F32(1)<<4, atype=TF32(2)<<7, btype=TF32(2)<<10, N/8<<17, M/16<<24
#define IDESC ((1u << 4) | (2u << 7) | (2u << 10) | ((BN / 8) << 17) | ((BM / 16) << 24))

// Pre-packed operands: exact SW64-swizzled smem images, slab-major, contiguous.
// g_A[f][slab16][m][16 floats]  (raw f32 emb bits)
// g_Wt[p][slab16][n][16 floats] (tf32-rounded W^T)
// SW64 swizzle of a 64B row: 16B-chunk c -> c ^ ((row>>1)&3)
__device__ float g_A [(size_t)NF * NITER * BATCH * BK];   // 33.5 MB
__device__ float g_Wt[(size_t)NP * NITER * EMB * BK];     // 31.5 MB

__device__ __forceinline__ float round_tf32(float v) {
    uint32_t u;
    asm("cvt.rna.tf32.f32 %0, %1;" : "=r"(u) : "f"(v));
    return __uint_as_float(u);
}

// ---------------- pack emb -> g_A (SW64 slab tiles) ----------------
// grid(slab=16, mb=16, f=16), block 256
__global__ void pack_a(const float* __restrict__ emb) {
    const int slab = blockIdx.x, mb = blockIdx.y, f = blockIdx.z;
    const int tid = threadIdx.x;
#pragma unroll
    for (int it = 0; it < 2; it++) {
        int idx = tid + it * 256;            // 0..511 (128 rows x 4 chunks)
        int m = idx >> 2, c = idx & 3;
        int gm = mb * 128 + m;
        const float4 v = *(const float4*)(emb + ((size_t)gm * NF + f) * EMB + slab * BK + c * 4);
        *(float4*)(g_A + (((size_t)f * NITER + slab) * BATCH + gm) * BK
                   + ((c ^ ((m >> 1) & 3)) << 2)) = v;
    }
}

// ---------------- pack W[p][k][n] -> g_Wt (transposed, rounded, SW64) ----------------
// grid(kb=8, nb=8, p=120), block (32,8)
__global__ void pack_w(const float* __restrict__ W) {
    __shared__ float t[32][33];
    const int kb = blockIdx.x;              // 32-k block -> two 16-k slabs
    const int nb = blockIdx.y * 32;
    const int p  = blockIdx.z;
    const float* Wp = W + (size_t)p * EMB * EMB;
    const int tx = threadIdx.x;
#pragma unroll
    for (int i = threadIdx.y; i < 32; i += 8)        // t[k_local][n_local]
        t[i][tx] = round_tf32(Wp[(size_t)(kb * 32 + i) * EMB + nb + tx]);
    __syncthreads();
#pragma unroll
    for (int i = threadIdx.y; i < 32; i += 8) {      // n = nb+i, k_local = tx
        const int n    = nb + i;
        const int slab = kb * 2 + (tx >> 4);
        const int kk   = tx & 15;
        const int c = kk >> 2, sub = kk & 3;
        g_Wt[(((size_t)p * NITER + slab) * EMB + n) * BK
             + ((c ^ ((n >> 1) & 3)) << 2) + sub] = t[tx][i];
    }
}

#if USE_TCGEN
// ---------------- tcgen05 / cluster helpers ----------------
__device__ __forceinline__ uint32_t smem_u32(const void* p) {
    uint32_t a;
    asm("{ .reg .u64 t; cvta.to.shared.u64 t, %1; cvt.u32.u64 %0, t; }" : "=r"(a) : "l"(p));
    return a;
}
__device__ __forceinline__ uint32_t elect_one() {
    uint32_t pred;
    asm volatile("{ .reg .pred p; elect.sync _|p, 0xFFFFFFFF; selp.b32 %0, 1, 0, p; }" : "=r"(pred));
    return pred;
}
__device__ __forceinline__ uint32_t cluster_rank() {
    uint32_t r;
    asm("mov.u32 %0, %%cluster_ctarank;" : "=r"(r));
    return r;
}
#define CLUSTER_ARRIVE() asm volatile("barrier.cluster.arrive.aligned;" ::: "memory")
#define CLUSTER_WAIT()   asm volatile("barrier.cluster.wait.aligned;" ::: "memory")
static __device__ __forceinline__ uint64_t make_desc(uint32_t addr) {
    // SW64 K-major: layout=4, version=1, SBO=32 (512B per 8-row block), LBO=1 (16B)
    return ((uint64_t)4 << 61) | ((uint64_t)1 << 46) | ((uint64_t)32 << 32) |
           ((uint64_t)1 << 16) | (((uint64_t)addr >> 4) & 0x3FFF);
}
#define MBAR_INIT(a, n) asm volatile("mbarrier.init.shared.b64 [%0], %1;" :: "r"(a), "r"(n) : "memory")
__device__ __forceinline__ void mbar_wait(uint32_t mbar, uint32_t parity) {
    uint32_t done;
    asm volatile(
        "{ .reg .pred p; mbarrier.try_wait.parity.acquire.cta.shared::cta.b64 p, [%1], %2; selp.b32 %0, 1, 0, p; }"
        : "=r"(done) : "r"(mbar), "r"(parity) : "memory");
    if (!done) {
        asm volatile(
            "{ .reg .pred P1;\n"
            "W_%=: mbarrier.try_wait.parity.acquire.cta.shared::cta.b64 P1, [%0], %1, 0x989680;\n"
            "@P1 bra.uni D_%=; bra.uni W_%=;\nD_%=: }"
            :: "r"(mbar), "r"(parity) : "memory");
    }
}
__device__ __forceinline__ void expect_tx(uint32_t mbar, uint32_t bytes) {
    asm volatile("mbarrier.arrive.expect_tx.shared.b64 _, [%0], %1;"
                 :: "r"(mbar), "r"(bytes) : "memory");
}
// bulk copy gmem -> smem (local), completion feeds tx-count of mbar
__device__ __forceinline__ void bulk_cp(uint32_t dst, const void* src, uint32_t bytes, uint32_t mbar) {
    asm volatile("cp.async.bulk.shared::cta.global.mbarrier::complete_tx::bytes [%0], [%1], %2, [%3];"
                 :: "r"(dst), "l"(src), "r"(bytes), "r"(mbar) : "memory");
}
// bulk copy gmem -> smem of every CTA in ctaMask (same offset); complete_tx delivered
// to the barrier at the same offset in each destination CTA.
__device__ __forceinline__ void bulk_cp_mc(uint32_t dst, const void* src, uint32_t bytes,
                                           uint32_t mbar, uint16_t mask) {
    asm volatile(
        "cp.async.bulk.shared::cluster.global.mbarrier::complete_tx::bytes.multicast::cluster "
        "[%0], [%1], %2, [%3], %4;"
        :: "r"(dst), "l"(src), "r"(bytes), "r"(mbar), "h"(mask) : "memory");
}
__device__ __forceinline__ void mma_tf32_ss(uint32_t d, uint64_t a, uint64_t b,
                                            uint32_t idesc, uint32_t en) {
    asm volatile(
        "{ .reg .pred p; setp.ne.u32 p, %4, 0;\n"
        "tcgen05.mma.cta_group::1.kind::tf32 [%0], %1, %2, %3, {%5,%5,%5,%5}, p; }"
        :: "r"(d), "l"(a), "l"(b), "r"(idesc), "r"(en), "r"(0u) : "memory");
}
#define TC_COMMIT(mbar) \
    asm volatile("tcgen05.commit.cta_group::1.mbarrier::arrive::one.shared::cluster.b64 [%0];" \
                 :: "r"(mbar) : "memory")
// multicast commit: on MMA completion, arrive on the barrier at the same offset in
// every CTA whose bit is set in mask.
#define TC_COMMIT_MC(mbar, mask) \
    asm volatile("tcgen05.commit.cta_group::1.mbarrier::arrive::one.shared::cluster.multicast::cluster.b64 [%0], %1;" \
                 :: "r"(mbar), "h"((uint16_t)(mask)) : "memory")
#define FENCE_ASYNC()     asm volatile("fence.proxy.async.shared::cta;" ::: "memory")
#define TC_FENCE_AFTER()  asm volatile("tcgen05.fence::after_thread_sync;" ::: "memory")
#define TC_FENCE_BEFORE() asm volatile("tcgen05.fence::before_thread_sync;" ::: "memory")
#define LDTM_X32(r, addr) \
    asm volatile("tcgen05.ld.sync.aligned.32x32b.x32.b32 " \
        "{%0,%1,%2,%3,%4,%5,%6,%7,%8,%9,%10,%11,%12,%13,%14,%15," \
        "%16,%17,%18,%19,%20,%21,%22,%23,%24,%25,%26,%27,%28,%29,%30,%31}, [%32];" \
        : "=r"((r)[0]),"=r"((r)[1]),"=r"((r)[2]),"=r"((r)[3]),"=r"((r)[4]),"=r"((r)[5]),"=r"((r)[6]),"=r"((r)[7]), \
          "=r"((r)[8]),"=r"((r)[9]),"=r"((r)[10]),"=r"((r)[11]),"=r"((r)[12]),"=r"((r)[13]),"=r"((r)[14]),"=r"((r)[15]), \
          "=r"((r)[16]),"=r"((r)[17]),"=r"((r)[18]),"=r"((r)[19]),"=r"((r)[20]),"=r"((r)[21]),"=r"((r)[22]),"=r"((r)[23]), \
          "=r"((r)[24]),"=r"((r)[25]),"=r"((r)[26]),"=r"((r)[27]),"=r"((r)[28]),"=r"((r)[29]),"=r"((r)[30]),"=r"((r)[31]) \
        : "r"(addr))
#define TC_WAIT_LD() asm volatile("tcgen05.wait::ld.sync.aligned;" ::: "memory")
#endif  // USE_TCGEN

#if !USE_TCGEN
// legacy mma.sync helpers (fallback cubin; not selected on GB300)
__device__ __forceinline__ uint32_t f2tf32(float v) {
    uint32_t u;
    asm("cvt.rna.tf32.f32 %0, %1;" : "=r"(u) : "f"(v));
    return u;
}
__device__ __forceinline__ void mma_tf32_16x8x8(float* d, const uint32_t* a, const uint32_t* b) {
    asm volatile(
        "mma.sync.aligned.m16n8k8.row.col.f32.tf32.tf32.f32 "
        "{%0,%1,%2,%3}, {%4,%5,%6,%7}, {%8,%9}, {%0,%1,%2,%3};"
        : "+f"(d[0]), "+f"(d[1]), "+f"(d[2]), "+f"(d[3])
        : "r"(a[0]), "r"(a[1]), "r"(a[2]), "r"(a[3]), "r"(b[0]), "r"(b[1]));
}
#endif

// ================= fused bilinear kernel: one symbol, two arch paths =================
// grid(16, 120), cluster (2,1,1) pairs m-blocks sharing p; block 256, smem SMEM_ALLOC
__global__ __launch_bounds__(256, 2) __cluster_dims__(2, 1, 1)
void bilinear_fused(const float* __restrict__ emb,
                    const float* __restrict__ weight,
                    const float* __restrict__ bias,
                    float* __restrict__ out) {
    const int tid = threadIdx.x;
    const int p   = blockIdx.y;
    // pair p -> (r_idx, c_idx) of triu_indices(16, 1)
    int r_idx = 0, rem = p;
    while (rem >= NF - 1 - r_idx) { rem -= NF - 1 - r_idx; r_idx++; }
    const int c_idx = r_idx + 1 + rem;
    const int m0 = blockIdx.x * BM;

#if USE_TCGEN
    // -------------------------------------------------- tcgen05 tf32 bulk-multicast pipeline
    extern __shared__ char smem_raw[];
    const uint32_t raw_u32 = smem_u32(smem_raw);
    const uint32_t base = (raw_u32 + 1023u) & ~1023u;
    const uint32_t pad  = base - raw_u32;
    const int wid  = tid >> 5;
    const int lane = tid & 31;

    const uint32_t full0  = base + MBAR_OFF;        // full[s]  = full0 + s*8
    const uint32_t empty0 = base + MBAR_OFF + 32;   // empty[s] = empty0 + s*8
    const uint32_t doneb  = base + MBAR_OFF + 64;   // final-MMA barrier (single phase)

    if (wid == 0) {
        asm volatile("tcgen05.alloc.cta_group::1.sync.aligned.shared::cta.b32 [%0], %1;"
                     :: "r"(base), "r"((uint32_t)TMEM_COLS) : "memory");
        // release the per-SM alloc permit immediately (else co-resident CTA serializes)
        asm volatile("tcgen05.relinquish_alloc_permit.cta_group::1.sync.aligned;");
    }
    if (tid == 0) {
#pragma unroll
        for (int s = 0; s < NSTAGE; s++) {
            MBAR_INIT(full0 + s * 8, 1);     // 1 arrival (local expect_tx) + tx bytes
            MBAR_INIT(empty0 + s * 8, 2);    // BOTH CTAs' multicast MMA commits per slab
        }
        MBAR_INIT(doneb, 1);                 // own final commit
    }
    __syncthreads();
    // peer barriers must be initialized before any multicast targets them
    CLUSTER_ARRIVE();
    CLUSTER_WAIT();

    uint32_t tmem;
    asm volatile("ld.shared.b32 %0, [%1];" : "=r"(tmem) : "r"(base));

    if (wid == 1) {
        // ---------------- producer: one elected thread of warp 1 ----------------
        // Loads own A locally; loads its HALF of B and multicasts it to both CTAs.
        if (elect_one()) {
            const uint32_t rank = cluster_rank();           // 0 or 1
            const float* Asrc = g_A + (((size_t)r_idx * NITER) * BATCH + m0) * BK;
            const float* Bsrc = g_Wt + ((size_t)p * NITER) * EMB * BK
                                + (size_t)rank * (EMB / 2) * BK;   // own 128-row half
            for (int j = 0; j < NITER; j++) {
                const int s = j & (NSTAGE - 1);
                if (j >= NSTAGE)            // slot reuse: wait BOTH CTAs' MMA of occupant j-NSTAGE
                    mbar_wait(empty0 + s * 8, ((j - NSTAGE) >> 2) & 1);
                const uint32_t st = base + STAGE0_OFF + s * STAGE_BYTES;
                expect_tx(full0 + s * 8, STAGE_BYTES);      // A 8K + own half 8K + peer half 8K
                bulk_cp(st, Asrc + (size_t)j * BATCH * BK, A_BYTES, full0 + s * 8);
                bulk_cp_mc(st + A_BYTES + rank * BHALF,
                           Bsrc + (size_t)j * EMB * BK, BHALF, full0 + s * 8, 0x3);
            }
        }
    } else if (wid == 0) {
        // ---------------- consumer: one elected thread of warp 0 ----------------
        if (elect_one()) {
            for (int it = 0; it < NITER; it++) {
                const int s = it & (NSTAGE - 1);
                mbar_wait(full0 + s * 8, (it >> 2) & 1);
                FENCE_ASYNC();
                const uint32_t st = base + STAGE0_OFF + s * STAGE_BYTES;
                const uint64_t ad = make_desc(st);
                const uint64_t bd = make_desc(st + A_BYTES);
#pragma unroll
                for (int jj = 0; jj < 2; jj++)       // 2 x (K=8) per 16-float slab
                    mma_tf32_ss(tmem, ad + jj * 2, bd + jj * 2, IDESC,
                                (it == 0 && jj == 0) ? 0u : 1u);
                // steady state: multicast commit -> both CTAs' empty[s] tick (count=2).
                // final iteration: local single-phase done barrier.
                if (it == NITER - 1) { TC_COMMIT(doneb); }
                else                 { TC_COMMIT_MC(empty0 + s * 8, 0x3); }
            }
        }
    }
    // warps 2-7 fall through directly to the final wait.

    // wait for own LAST MMA (single-phase barrier, parity 0).
    // All peer multicasts into this CTA's smem completed before full[3] -> safe to reuse smem.
    mbar_wait(doneb, 0);
    TC_FENCE_AFTER();

    // ---------------- epilogue: smem-staged, fully coalesced q loads / out stores ----------------
    {
        float* q_s   = (float*)(smem_raw + pad + Q_S_OFF);     // [128][EPI_STRIDE]
        float* out_s = (float*)(smem_raw + pad + OUT_S_OFF);   // [128][EPI_STRIDE]
        const float* brow = bias + (size_t)p * EMB;
        const int sub  = wid & 3;                 // TMEM row subpartition (rows sub*32+lane)
        const int colw = (wid >> 2) * 32;         // col offset within the 64-col chunk
        const int mrow = sub * 32 + lane;

#pragma unroll
        for (int ch = 0; ch < 4; ch++) {
            const int c0 = ch * 64;               // global col base of this chunk
            __syncthreads();                       // protect buffer reuse across chunks
            // stage q tile [128 x 64], coalesced: 16 lanes per row, 256B runs
#pragma unroll
            for (int i = 0; i < 8; i++) {
                int idx = tid + i * 256;           // 0..2047
                int row = idx >> 4, c4 = idx & 15;
                const float4 v = *(const float4*)(emb + ((size_t)(m0 + row) * NF + c_idx) * EMB + c0 + c4 * 4);
                float* d = q_s + row * EPI_STRIDE + c4 * 4;
                d[0] = v.x; d[1] = v.y; d[2] = v.z; d[3] = v.w;
            }
            __syncthreads();
            // LDTM 32 cols per warp + multiply + stage out
            {
                uint32_t r[32];
                LDTM_X32(r, tmem + c0 + colw);
                TC_WAIT_LD();
                const float* qs = q_s   + mrow * EPI_STRIDE + colw;
                float*       os = out_s + mrow * EPI_STRIDE + colw;
#pragma unroll
                for (int jj = 0; jj < 8; jj++) {
                    const float4 bb = *(const float4*)(brow + c0 + colw + jj * 4);
                    os[jj * 4 + 0] = __uint_as_float(r[jj * 4 + 0]) * qs[jj * 4 + 0] + bb.x;
                    os[jj * 4 + 1] = __uint_as_float(r[jj * 4 + 1]) * qs[jj * 4 + 1] + bb.y;
                    os[jj * 4 + 2] = __uint_as_float(r[jj * 4 + 2]) * qs[jj * 4 + 2] + bb.z;
                    os[jj * 4 + 3] = __uint_as_float(r[jj * 4 + 3]) * qs[jj * 4 + 3] + bb.w;
                }
            }
            __syncthreads();
            // store out tile [128 x 64], coalesced float4 stores
#pragma unroll
            for (int i = 0; i < 8; i++) {
                int idx = tid + i * 256;
                int row = idx >> 4, c4 = idx & 15;
                const float* s = out_s + row * EPI_STRIDE + c4 * 4;
                float4 v; v.x = s[0]; v.y = s[1]; v.z = s[2]; v.w = s[3];
                *(float4*)(out + ((size_t)(m0 + row) * NP + p) * EMB + c0 + c4 * 4) = v;
            }
        }
    }
    TC_FENCE_BEFORE();
    __syncthreads();
    if (wid == 0) {
        asm volatile("tcgen05.dealloc.cta_group::1.sync.aligned.b32 %0, %1;"
                     :: "r"(tmem), "r"((uint32_t)TMEM_COLS));
    }
    // exit hygiene: no CTA leaves while its pair could still be referenced
    __syncthreads();
    CLUSTER_ARRIVE();
    CLUSTER_WAIT();

#else
    // -------------------------------------------------- legacy mma.sync tf32 fallback
    // covers the 128x256 CTA tile as two 128x128 passes (uses raw weight; BK32 tiles)
    __shared__ uint32_t As[32 * 132];
    __shared__ uint32_t Bs[32 * 132];
    const int lane = tid & 31;
    const int warp = tid >> 5;
    const int warp_m = warp & 3;
    const int warp_n = warp >> 2;
    const float* Wp = weight + (size_t)p * EMB * EMB;
    const int lr = lane >> 2;
    const int lc = lane & 3;

    for (int nb = 0; nb < 2; nb++) {
        const int n0 = nb * 128;
        float acc[2][8][4];
#pragma unroll
        for (int i = 0; i < 2; i++)
#pragma unroll
            for (int j = 0; j < 8; j++)
#pragma unroll
                for (int r = 0; r < 4; r++) acc[i][j][r] = 0.0f;

        for (int k0 = 0; k0 < EMB; k0 += 32) {
            __syncthreads();
#pragma unroll
            for (int it = 0; it < 4; it++) {
                int fid = tid + it * 256;
                int m   = fid >> 3;
                int k4  = fid & 7;
                const float4 v = *(const float4*)(emb + ((size_t)(m0 + m) * NF + r_idx) * EMB + k0 + k4 * 4);
                As[(k4 * 4 + 0) * 132 + m] = f2tf32(v.x);
                As[(k4 * 4 + 1) * 132 + m] = f2tf32(v.y);
                As[(k4 * 4 + 2) * 132 + m] = f2tf32(v.z);
                As[(k4 * 4 + 3) * 132 + m] = f2tf32(v.w);
            }
#pragma unroll
            for (int it = 0; it < 4; it++) {
                int fid = tid + it * 256;
                int k   = fid >> 5;
                int n4  = fid & 31;
                const float4 w = *(const float4*)(Wp + (size_t)(k0 + k) * EMB + n0 + n4 * 4);
                Bs[k * 132 + n4 * 4 + 0] = f2tf32(w.x);
                Bs[k * 132 + n4 * 4 + 1] = f2tf32(w.y);
                Bs[k * 132 + n4 * 4 + 2] = f2tf32(w.z);
                Bs[k * 132 + n4 * 4 + 3] = f2tf32(w.w);
            }
            __syncthreads();

#pragma unroll
            for (int kk = 0; kk < 32; kk += 8) {
                uint32_t a[2][4];
                uint32_t b[8][2];
#pragma unroll
                for (int i = 0; i < 2; i++) {
                    int mbase = warp_m * 32 + i * 16 + lr;
                    a[i][0] = As[(kk + lc) * 132 + mbase];
                    a[i][1] = As[(kk + lc) * 132 + mbase + 8];
                    a[i][2] = As[(kk + lc + 4) * 132 + mbase];
                    a[i][3] = As[(kk + lc + 4) * 132 + mbase + 8];
                }
#pragma unroll
                for (int j = 0; j < 8; j++) {
                    int nbase = warp_n * 64 + j * 8 + lr;
                    b[j][0] = Bs[(kk + lc) * 132 + nbase];
                    b[j][1] = Bs[(kk + lc + 4) * 132 + nbase];
                }
#pragma unroll
                for (int i = 0; i < 2; i++)
#pragma unroll
                    for (int j = 0; j < 8; j++)
                        mma_tf32_16x8x8(acc[i][j], a[i], b[j]);
            }
        }

#pragma unroll
        for (int i = 0; i < 2; i++) {
            const int gm0 = m0 + warp_m * 32 + i * 16 + lr;
#pragma unroll
            for (int j = 0; j < 8; j++) {
                const int gn = n0 + warp_n * 64 + j * 8 + lc * 2;
                const float2 bs = *(const float2*)(bias + (size_t)p * EMB + gn);

                const float2 q0 = *(const float2*)(emb + ((size_t)gm0 * NF + c_idx) * EMB + gn);
                float2 o0;
                o0.x = acc[i][j][0] * q0.x + bs.x;
                o0.y = acc[i][j][1] * q0.y + bs.y;
                *(float2*)(out + ((size_t)gm0 * NP + p) * EMB + gn) = o0;

                const float2 q1 = *(const float2*)(emb + ((size_t)(gm0 + 8) * NF + c_idx) * EMB + gn);
                float2 o1;
                o1.x = acc[i][j][2] * q1.x + bs.x;
                o1.y = acc[i][j][3] * q1.y + bs.y;
                *(float2*)(out + ((size_t)(gm0 + 8) * NP + p) * EMB + gn) = o1;
            }
        }
        __syncthreads();
    }
#endif
}

extern "C" void kernel_launch(void* const* d_in, const int* in_sizes, int n_in,
                              void* d_out, int out_size) {
    const float* emb    = (const float*)d_in[0];
    const float* weight = (const float*)d_in[1];
    const float* bias   = (const float*)d_in[2];
    float* out          = (float*)d_out;

    cudaFuncSetAttribute(bilinear_fused, cudaFuncAttributeMaxDynamicSharedMemorySize, SMEM_ALLOC);

    pack_a<<<dim3(NITER, BATCH / BM, NF), 256>>>(emb);
    pack_w<<<dim3(8, EMB / 32, NP), dim3(32, 8)>>>(weight);
    bilinear_fused<<<dim3(BATCH / BM, NP), 256, SMEM_ALLOC>>>(emb, weight, bias, out);
}